// round 1
// baseline (speedup 1.0000x reference)
#include <cuda_runtime.h>
#include <math.h>

#define Bb 4
#define Ss 1024
#define Ee 1024
#define Hh 16
#define HD 64
#define BH (Bb*Hh)

// ---------------- scratch (no allocs allowed) ----------------
__device__ float g_q[BH * Ss * HD];          // 16 MB
__device__ float g_k[BH * Ss * HD];          // 16 MB
__device__ float g_v[BH * Ss * HD];          // 16 MB
__device__ float g_ctx[Bb * Ss * Ee];        // 16 MB
__device__ float g_attn[67108864];           // 256 MB fallback if attn not in d_out

// ---------------- generic NT GEMM: C[m][n] = sum_k A[m][k]*W[n][k] + bias[n] ----------------
// 64x64 tile, BK=16, 256 threads, 4x4 micro-tile.
// splitHeads=1: scatter n into (B,H,S,HD) layout (head-split projections).
__global__ void __launch_bounds__(256) gemm_nt_kernel(
    const float* __restrict__ A, const float* __restrict__ W,
    const float* __restrict__ bias, float* __restrict__ C,
    int M, int N, int K, int splitHeads)
{
    __shared__ float As[16][68];
    __shared__ float Bs[16][68];
    const int tid = threadIdx.x;
    const int bm = blockIdx.y * 64;
    const int bn = blockIdx.x * 64;
    const int tx = tid & 15;
    const int ty = tid >> 4;
    const int lr = tid >> 2;
    const int lk = (tid & 3) << 2;

    float acc[4][4];
#pragma unroll
    for (int i = 0; i < 4; i++)
#pragma unroll
        for (int j = 0; j < 4; j++) acc[i][j] = 0.f;

    const float* Aptr = A + (size_t)(bm + lr) * K + lk;
    const float* Wptr = W + (size_t)(bn + lr) * K + lk;

    for (int k0 = 0; k0 < K; k0 += 16) {
        float4 a = *reinterpret_cast<const float4*>(Aptr + k0);
        float4 b = *reinterpret_cast<const float4*>(Wptr + k0);
        As[lk + 0][lr] = a.x; As[lk + 1][lr] = a.y; As[lk + 2][lr] = a.z; As[lk + 3][lr] = a.w;
        Bs[lk + 0][lr] = b.x; Bs[lk + 1][lr] = b.y; Bs[lk + 2][lr] = b.z; Bs[lk + 3][lr] = b.w;
        __syncthreads();
#pragma unroll
        for (int kk = 0; kk < 16; kk++) {
            float4 av = *reinterpret_cast<const float4*>(&As[kk][ty << 2]);
            float4 bv = *reinterpret_cast<const float4*>(&Bs[kk][tx << 2]);
            float am[4] = {av.x, av.y, av.z, av.w};
            float bm_[4] = {bv.x, bv.y, bv.z, bv.w};
#pragma unroll
            for (int i = 0; i < 4; i++)
#pragma unroll
                for (int j = 0; j < 4; j++)
                    acc[i][j] = fmaf(am[i], bm_[j], acc[i][j]);
        }
        __syncthreads();
    }

#pragma unroll
    for (int i = 0; i < 4; i++) {
        int m = bm + (ty << 2) + i;
#pragma unroll
        for (int j = 0; j < 4; j++) {
            int n = bn + (tx << 2) + j;
            float v = acc[i][j] + bias[n];
            if (splitHeads) {
                int b = m / Ss, s = m % Ss;
                int h = n / HD, d = n % HD;
                C[(((size_t)(b * Hh + h)) * Ss + s) * HD + d] = v;
            } else {
                C[(size_t)m * N + n] = v;
            }
        }
    }
}

// ---------------- scores: attn_raw[bh][q][k] = (q.k)/8, causal-masked -> 0 ----------------
__global__ void __launch_bounds__(256) scores_kernel(
    const float* __restrict__ Q, const float* __restrict__ Kh,
    float* __restrict__ attn)
{
    const int bh = blockIdx.z;
    const int qm = blockIdx.y * 64;
    const int kn = blockIdx.x * 64;
    const int tid = threadIdx.x;
    float* out = attn + (size_t)bh * Ss * Ss;

    if (kn > qm + 63) {
        // fully masked tile: write zeros (output must be fully written each replay)
        float4 z = make_float4(0.f, 0.f, 0.f, 0.f);
#pragma unroll
        for (int r = 0; r < 4; r++) {
            int idx = tid + r * 256;      // float4 index within 64x64 tile
            int row = idx >> 4;
            int c4 = (idx & 15) << 2;
            *reinterpret_cast<float4*>(out + (size_t)(qm + row) * Ss + kn + c4) = z;
        }
        return;
    }

    __shared__ float As[16][68];
    __shared__ float Bs[16][68];
    const int tx = tid & 15;
    const int ty = tid >> 4;
    const int lr = tid >> 2;
    const int lk = (tid & 3) << 2;

    float acc[4][4];
#pragma unroll
    for (int i = 0; i < 4; i++)
#pragma unroll
        for (int j = 0; j < 4; j++) acc[i][j] = 0.f;

    const float* Aptr = Q + (size_t)bh * Ss * HD + (size_t)(qm + lr) * HD + lk;
    const float* Bptr = Kh + (size_t)bh * Ss * HD + (size_t)(kn + lr) * HD + lk;

    for (int k0 = 0; k0 < HD; k0 += 16) {
        float4 a = *reinterpret_cast<const float4*>(Aptr + k0);
        float4 b = *reinterpret_cast<const float4*>(Bptr + k0);
        As[lk + 0][lr] = a.x; As[lk + 1][lr] = a.y; As[lk + 2][lr] = a.z; As[lk + 3][lr] = a.w;
        Bs[lk + 0][lr] = b.x; Bs[lk + 1][lr] = b.y; Bs[lk + 2][lr] = b.z; Bs[lk + 3][lr] = b.w;
        __syncthreads();
#pragma unroll
        for (int kk = 0; kk < 16; kk++) {
            float4 av = *reinterpret_cast<const float4*>(&As[kk][ty << 2]);
            float4 bv = *reinterpret_cast<const float4*>(&Bs[kk][tx << 2]);
            float am[4] = {av.x, av.y, av.z, av.w};
            float bm_[4] = {bv.x, bv.y, bv.z, bv.w};
#pragma unroll
            for (int i = 0; i < 4; i++)
#pragma unroll
                for (int j = 0; j < 4; j++)
                    acc[i][j] = fmaf(am[i], bm_[j], acc[i][j]);
        }
        __syncthreads();
    }

#pragma unroll
    for (int i = 0; i < 4; i++) {
        int row = qm + (ty << 2) + i;
#pragma unroll
        for (int j = 0; j < 4; j++) {
            int col = kn + (tx << 2) + j;
            out[(size_t)row * Ss + col] = (col <= row) ? acc[i][j] * 0.125f : 0.0f;
        }
    }
}

// ---------------- softmax: per-row over k in [0, q], in-place ----------------
__global__ void __launch_bounds__(256) softmax_kernel(float* __restrict__ attn)
{
    const int row = blockIdx.x;          // = bh*S + q
    const int q = row & (Ss - 1);
    float* p = attn + (size_t)row * Ss;
    __shared__ float buf[Ss];
    __shared__ float red[256];
    const int tid = threadIdx.x;
    const int n = q + 1;

    float mx = -INFINITY;
    for (int i = tid; i < n; i += 256) {
        float v = p[i];
        buf[i] = v;
        mx = fmaxf(mx, v);
    }
    red[tid] = mx;
    __syncthreads();
#pragma unroll
    for (int s = 128; s > 0; s >>= 1) {
        if (tid < s) red[tid] = fmaxf(red[tid], red[tid + s]);
        __syncthreads();
    }
    mx = red[0];
    __syncthreads();

    float sum = 0.f;
    for (int i = tid; i < n; i += 256) {
        float e = __expf(buf[i] - mx);
        buf[i] = e;
        sum += e;
    }
    red[tid] = sum;
    __syncthreads();
#pragma unroll
    for (int s = 128; s > 0; s >>= 1) {
        if (tid < s) red[tid] += red[tid + s];
        __syncthreads();
    }
    float inv = 1.0f / red[0];

    for (int i = tid; i < n; i += 256) p[i] = buf[i] * inv;
}

// ---------------- ctx: ctx_merged[b][s][h*64+d] = sum_k attn[bh][s][k] * v[bh][k][d] ----------------
__global__ void __launch_bounds__(256) ctx_kernel(
    const float* __restrict__ attn, const float* __restrict__ V,
    float* __restrict__ ctx)
{
    const int bh = blockIdx.z;
    const int qm = blockIdx.y * 64;
    const int tid = threadIdx.x;
    const float* A = attn + (size_t)bh * Ss * Ss;
    const float* Bm = V + (size_t)bh * Ss * HD;

    __shared__ float As[16][68];
    __shared__ float Bs[16][68];
    const int tx = tid & 15;
    const int ty = tid >> 4;
    const int lr = tid >> 2;
    const int lk = (tid & 3) << 2;
    const int br = tid >> 4;            // 0..15 : k-row within tile
    const int bc = (tid & 15) << 2;     // 0..60 : d-col

    float acc[4][4];
#pragma unroll
    for (int i = 0; i < 4; i++)
#pragma unroll
        for (int j = 0; j < 4; j++) acc[i][j] = 0.f;

    const int kmax = qm + 64;           // causal: attn[q][k]=0 for k>q
    for (int k0 = 0; k0 < kmax; k0 += 16) {
        float4 a = *reinterpret_cast<const float4*>(A + (size_t)(qm + lr) * Ss + k0 + lk);
        As[lk + 0][lr] = a.x; As[lk + 1][lr] = a.y; As[lk + 2][lr] = a.z; As[lk + 3][lr] = a.w;
        float4 b = *reinterpret_cast<const float4*>(Bm + (size_t)(k0 + br) * HD + bc);
        *reinterpret_cast<float4*>(&Bs[br][bc]) = b;
        __syncthreads();
#pragma unroll
        for (int kk = 0; kk < 16; kk++) {
            float4 av = *reinterpret_cast<const float4*>(&As[kk][ty << 2]);
            float4 bv = *reinterpret_cast<const float4*>(&Bs[kk][tx << 2]);
            float am[4] = {av.x, av.y, av.z, av.w};
            float bm_[4] = {bv.x, bv.y, bv.z, bv.w};
#pragma unroll
            for (int i = 0; i < 4; i++)
#pragma unroll
                for (int j = 0; j < 4; j++)
                    acc[i][j] = fmaf(am[i], bm_[j], acc[i][j]);
        }
        __syncthreads();
    }

    const int b = bh >> 4;
    const int h = bh & 15;
#pragma unroll
    for (int i = 0; i < 4; i++) {
        int s = qm + (ty << 2) + i;
#pragma unroll
        for (int j = 0; j < 4; j++) {
            int d = (tx << 2) + j;
            ctx[((size_t)(b * Ss + s)) * Ee + h * HD + d] = acc[i][j];
        }
    }
}

// ---------------- launch ----------------
extern "C" void kernel_launch(void* const* d_in, const int* in_sizes, int n_in,
                              void* d_out, int out_size)
{
    const float* query = (const float*)d_in[0];
    const float* key_t = (const float*)d_in[1];
    const float* value = (const float*)d_in[2];
    // d_in[3] = mask (causal tril, hardcoded in kernels)
    const float* Wq = (const float*)d_in[4];
    const float* bq = (const float*)d_in[5];
    const float* Wk = (const float*)d_in[6];
    const float* bk = (const float*)d_in[7];
    const float* Wv = (const float*)d_in[8];
    const float* bv = (const float*)d_in[9];
    const float* Wo = (const float*)d_in[10];
    const float* bo = (const float*)d_in[11];
    float* out = (float*)d_out;

    float *qp, *kp, *vp, *ctxp, *attn_fallback;
    cudaGetSymbolAddress((void**)&qp, g_q);
    cudaGetSymbolAddress((void**)&kp, g_k);
    cudaGetSymbolAddress((void**)&vp, g_v);
    cudaGetSymbolAddress((void**)&ctxp, g_ctx);
    cudaGetSymbolAddress((void**)&attn_fallback, g_attn);

    const long long needed = (long long)Bb * Ss * Ee + (long long)BH * Ss * Ss;
    float* attnp = ((long long)out_size >= needed) ? (out + (size_t)Bb * Ss * Ee)
                                                   : attn_fallback;

    dim3 blk(256);
    dim3 gproj(Ee / 64, (Bb * Ss) / 64);          // 16 x 64

    // QKV projections (split-head output layout)
    gemm_nt_kernel<<<gproj, blk>>>(query, Wq, bq, qp, Bb * Ss, Ee, Ee, 1);
    gemm_nt_kernel<<<gproj, blk>>>(key_t, Wk, bk, kp, Bb * Ss, Ee, Ee, 1);
    gemm_nt_kernel<<<gproj, blk>>>(value, Wv, bv, vp, Bb * Ss, Ee, Ee, 1);

    // scores (causal masked, scaled)
    dim3 gs(Ss / 64, Ss / 64, BH);                // 16 x 16 x 64
    scores_kernel<<<gs, blk>>>(qp, kp, attnp);

    // softmax per row
    softmax_kernel<<<BH * Ss, blk>>>(attnp);

    // ctx = attn @ V, merged-head layout
    dim3 gc(1, Ss / 64, BH);
    ctx_kernel<<<gc, blk>>>(attnp, vp, ctxp);

    // output projection
    gemm_nt_kernel<<<gproj, blk>>>(ctxp, Wo, bo, out, Bb * Ss, Ee, Ee, 0);
}

// round 3
// speedup vs baseline: 1.5776x; 1.5776x over previous
#include <cuda_runtime.h>
#include <cuda_bf16.h>
#include <math.h>
#include <stdint.h>

#define Bb 4
#define Ss 1024
#define Ee 1024
#define Hh 16
#define HD 64
#define BH (Bb*Hh)

// ---------------- scratch (no allocs allowed) ----------------
__device__ float g_q[BH * Ss * HD];
__device__ float g_k[BH * Ss * HD];
__device__ float g_v[BH * Ss * HD];
__device__ float g_ctx[Bb * Ss * Ee];
__device__ float g_attn[67108864];               // fallback if attn not in d_out
__device__ __nv_bfloat16 g_ahi[Bb * Ss * Ee];
__device__ __nv_bfloat16 g_alo[Bb * Ss * Ee];
__device__ __nv_bfloat16 g_whi[Ee * Ee];
__device__ __nv_bfloat16 g_wlo[Ee * Ee];

// ==================== helpers ====================
static __device__ __forceinline__ uint32_t s2u(const void* p) {
    uint32_t a;
    asm("{ .reg .u64 t; cvta.to.shared.u64 t, %1; cvt.u32.u64 %0, t; }" : "=r"(a) : "l"(p));
    return a;
}

static __device__ __forceinline__ void cp16(uint32_t saddr, const void* g) {
    asm volatile("cp.async.cg.shared.global [%0], [%1], 16;" :: "r"(saddr), "l"(g) : "memory");
}

static __device__ __forceinline__ void mma_bf16(float c[4], const uint32_t a[4], const uint32_t b[2]) {
    asm volatile(
        "mma.sync.aligned.m16n8k16.row.col.f32.bf16.bf16.f32 "
        "{%0,%1,%2,%3}, {%4,%5,%6,%7}, {%8,%9}, {%0,%1,%2,%3};"
        : "+f"(c[0]), "+f"(c[1]), "+f"(c[2]), "+f"(c[3])
        : "r"(a[0]), "r"(a[1]), "r"(a[2]), "r"(a[3]), "r"(b[0]), "r"(b[1]));
}

// ==================== split: x -> (hi=bf16(x), lo=bf16(x-hi)) ====================
__global__ void __launch_bounds__(256) split_bf16(
    const float4* __restrict__ x, __nv_bfloat16* __restrict__ hi,
    __nv_bfloat16* __restrict__ lo, int n4)
{
    int i = blockIdx.x * 256 + threadIdx.x;
    if (i >= n4) return;
    float4 v = x[i];
    __nv_bfloat16 h0 = __float2bfloat16(v.x);
    __nv_bfloat16 h1 = __float2bfloat16(v.y);
    __nv_bfloat16 h2 = __float2bfloat16(v.z);
    __nv_bfloat16 h3 = __float2bfloat16(v.w);
    __nv_bfloat16 l0 = __float2bfloat16(v.x - __bfloat162float(h0));
    __nv_bfloat16 l1 = __float2bfloat16(v.y - __bfloat162float(h1));
    __nv_bfloat16 l2 = __float2bfloat16(v.z - __bfloat162float(h2));
    __nv_bfloat16 l3 = __float2bfloat16(v.w - __bfloat162float(h3));
    ushort4 hs = make_ushort4(__bfloat16_as_ushort(h0), __bfloat16_as_ushort(h1),
                              __bfloat16_as_ushort(h2), __bfloat16_as_ushort(h3));
    ushort4 ls = make_ushort4(__bfloat16_as_ushort(l0), __bfloat16_as_ushort(l1),
                              __bfloat16_as_ushort(l2), __bfloat16_as_ushort(l3));
    *reinterpret_cast<ushort4*>(hi + 4 * (size_t)i) = hs;
    *reinterpret_cast<ushort4*>(lo + 4 * (size_t)i) = ls;
}

// ==================== bf16x3 mma GEMM ====================
// C[4096,1024] = A[4096,1024] @ W[1024,1024]^T + bias via Ahi*Whi + Ahi*Wlo + Alo*Whi.
// Tile 128x128, BK=32 bf16, 8 warps (4m x 2n), cp.async double-buffered.
// smem per stage: 4 arrays x [128 rows][20 u32] (16 used + 4 pad; conflict-free frag LDS).
#define ARR_B   10240
#define STAGE_B 40960
#define GEMM_SMEM (2 * STAGE_B)

__global__ void __launch_bounds__(256, 1) gemm_mma(
    const __nv_bfloat16* __restrict__ Ahi, const __nv_bfloat16* __restrict__ Alo,
    const __nv_bfloat16* __restrict__ Whi, const __nv_bfloat16* __restrict__ Wlo,
    const float* __restrict__ bias, float* __restrict__ C, int splitHeads)
{
    extern __shared__ __align__(128) char smem[];
    const uint32_t sb = s2u(smem);
    const int tid = threadIdx.x;
    const int lane = tid & 31, wid = tid >> 5;
    const int wm = wid & 3, wn = wid >> 2;
    const int bm = blockIdx.y << 7, bn = blockIdx.x << 7;
    const int K = 1024;

    // per-thread load slots: 2 chunks of 16B per array per stage
    const int c0 = tid << 1;
    const int lrow = c0 >> 2, lcc = c0 & 3;
    const __nv_bfloat16* pAh = Ahi + (size_t)(bm + lrow) * K + lcc * 8;
    const __nv_bfloat16* pAl = Alo + (size_t)(bm + lrow) * K + lcc * 8;
    const __nv_bfloat16* pWh = Whi + (size_t)(bn + lrow) * K + lcc * 8;
    const __nv_bfloat16* pWl = Wlo + (size_t)(bn + lrow) * K + lcc * 8;
    const uint32_t so = (uint32_t)(lrow * 80 + lcc * 16);

#define LOAD_STAGE(s, kt) do {                                          \
        uint32_t b_ = sb + (uint32_t)(s) * STAGE_B + so;                \
        const int ko_ = (kt) * 32;                                      \
        cp16(b_ + 0 * ARR_B,      pAh + ko_);                           \
        cp16(b_ + 0 * ARR_B + 16, pAh + ko_ + 8);                       \
        cp16(b_ + 1 * ARR_B,      pAl + ko_);                           \
        cp16(b_ + 1 * ARR_B + 16, pAl + ko_ + 8);                       \
        cp16(b_ + 2 * ARR_B,      pWh + ko_);                           \
        cp16(b_ + 2 * ARR_B + 16, pWh + ko_ + 8);                       \
        cp16(b_ + 3 * ARR_B,      pWl + ko_);                           \
        cp16(b_ + 3 * ARR_B + 16, pWl + ko_ + 8);                       \
        asm volatile("cp.async.commit_group;" ::: "memory");            \
    } while (0)

    float acc[2][8][4];
#pragma unroll
    for (int a = 0; a < 2; a++)
#pragma unroll
        for (int b = 0; b < 8; b++)
#pragma unroll
            for (int c = 0; c < 4; c++) acc[a][b][c] = 0.f;

    LOAD_STAGE(0, 0);

    const int fr = lane >> 2, fq = lane & 3;

    for (int kt = 0; kt < 32; kt++) {
        const int s = kt & 1;
        if (kt < 31) {
            LOAD_STAGE(s ^ 1, kt + 1);
            asm volatile("cp.async.wait_group 1;" ::: "memory");
        } else {
            asm volatile("cp.async.wait_group 0;" ::: "memory");
        }
        __syncthreads();

        const uint32_t* SAh = (const uint32_t*)(smem + (size_t)s * STAGE_B);
        const uint32_t* SAl = SAh + ARR_B / 4;
        const uint32_t* SWh = SAh + 2 * ARR_B / 4;
        const uint32_t* SWl = SAh + 3 * ARR_B / 4;

#pragma unroll
        for (int ks = 0; ks < 2; ks++) {
            const int w0 = ks * 8 + fq;
            uint32_t ah[2][4], al[2][4];
#pragma unroll
            for (int mt = 0; mt < 2; mt++) {
                int ra = wm * 32 + mt * 16 + fr;
                ah[mt][0] = SAh[ra * 20 + w0];
                ah[mt][1] = SAh[(ra + 8) * 20 + w0];
                ah[mt][2] = SAh[ra * 20 + w0 + 4];
                ah[mt][3] = SAh[(ra + 8) * 20 + w0 + 4];
                al[mt][0] = SAl[ra * 20 + w0];
                al[mt][1] = SAl[(ra + 8) * 20 + w0];
                al[mt][2] = SAl[ra * 20 + w0 + 4];
                al[mt][3] = SAl[(ra + 8) * 20 + w0 + 4];
            }
            uint32_t bh[8][2], bl[8][2];
#pragma unroll
            for (int nt = 0; nt < 8; nt++) {
                int rb = wn * 64 + nt * 8 + fr;
                bh[nt][0] = SWh[rb * 20 + w0];
                bh[nt][1] = SWh[rb * 20 + w0 + 4];
                bl[nt][0] = SWl[rb * 20 + w0];
                bl[nt][1] = SWl[rb * 20 + w0 + 4];
            }
#pragma unroll
            for (int mt = 0; mt < 2; mt++)
#pragma unroll
                for (int nt = 0; nt < 8; nt++) {
                    mma_bf16(acc[mt][nt], ah[mt], bh[nt]);
                    mma_bf16(acc[mt][nt], ah[mt], bl[nt]);
                    mma_bf16(acc[mt][nt], al[mt], bh[nt]);
                }
        }
        __syncthreads();
    }

    // epilogue
    const int q2 = (lane & 3) * 2;
#pragma unroll
    for (int mt = 0; mt < 2; mt++) {
#pragma unroll
        for (int i = 0; i < 2; i++) {
            int m = bm + wm * 32 + mt * 16 + fr + i * 8;
#pragma unroll
            for (int nt = 0; nt < 8; nt++) {
                int n = bn + wn * 64 + nt * 8 + q2;
                float2 v;
                v.x = acc[mt][nt][i * 2 + 0] + bias[n];
                v.y = acc[mt][nt][i * 2 + 1] + bias[n + 1];
                size_t idx;
                if (splitHeads) {
                    idx = ((((size_t)(m >> 10) * Hh + (n >> 6)) * Ss + (size_t)(m & 1023)) << 6)
                        + (n & 63);
                } else {
                    idx = (size_t)m * Ee + n;
                }
                *reinterpret_cast<float2*>(C + idx) = v;
            }
        }
    }
#undef LOAD_STAGE
}

// ==================== scores (SIMT) ====================
__global__ void __launch_bounds__(256) scores_kernel(
    const float* __restrict__ Q, const float* __restrict__ Kh, float* __restrict__ attn)
{
    const int bh = blockIdx.z;
    const int qm = blockIdx.y * 64;
    const int kn = blockIdx.x * 64;
    const int tid = threadIdx.x;
    float* out = attn + (size_t)bh * Ss * Ss;

    if (kn > qm + 63) {
        float4 z = make_float4(0.f, 0.f, 0.f, 0.f);
#pragma unroll
        for (int r = 0; r < 4; r++) {
            int idx = tid + r * 256;
            int row = idx >> 4;
            int c4 = (idx & 15) << 2;
            *reinterpret_cast<float4*>(out + (size_t)(qm + row) * Ss + kn + c4) = z;
        }
        return;
    }

    __shared__ float As[16][68];
    __shared__ float Bs[16][68];
    const int tx = tid & 15;
    const int ty = tid >> 4;
    const int lr = tid >> 2;
    const int lk = (tid & 3) << 2;

    float acc[4][4];
#pragma unroll
    for (int i = 0; i < 4; i++)
#pragma unroll
        for (int j = 0; j < 4; j++) acc[i][j] = 0.f;

    const float* Aptr = Q + (size_t)bh * Ss * HD + (size_t)(qm + lr) * HD + lk;
    const float* Bptr = Kh + (size_t)bh * Ss * HD + (size_t)(kn + lr) * HD + lk;

    for (int k0 = 0; k0 < HD; k0 += 16) {
        float4 a = *reinterpret_cast<const float4*>(Aptr + k0);
        float4 b = *reinterpret_cast<const float4*>(Bptr + k0);
        As[lk + 0][lr] = a.x; As[lk + 1][lr] = a.y; As[lk + 2][lr] = a.z; As[lk + 3][lr] = a.w;
        Bs[lk + 0][lr] = b.x; Bs[lk + 1][lr] = b.y; Bs[lk + 2][lr] = b.z; Bs[lk + 3][lr] = b.w;
        __syncthreads();
#pragma unroll
        for (int kk = 0; kk < 16; kk++) {
            float4 av = *reinterpret_cast<const float4*>(&As[kk][ty << 2]);
            float4 bv = *reinterpret_cast<const float4*>(&Bs[kk][tx << 2]);
            float am[4] = {av.x, av.y, av.z, av.w};
            float bm_[4] = {bv.x, bv.y, bv.z, bv.w};
#pragma unroll
            for (int i = 0; i < 4; i++)
#pragma unroll
                for (int j = 0; j < 4; j++)
                    acc[i][j] = fmaf(am[i], bm_[j], acc[i][j]);
        }
        __syncthreads();
    }

#pragma unroll
    for (int i = 0; i < 4; i++) {
        int row = qm + (ty << 2) + i;
#pragma unroll
        for (int j = 0; j < 4; j++) {
            int col = kn + (tx << 2) + j;
            out[(size_t)row * Ss + col] = (col <= row) ? acc[i][j] * 0.125f : 0.0f;
        }
    }
}

// ==================== softmax ====================
__global__ void __launch_bounds__(256) softmax_kernel(float* __restrict__ attn)
{
    const int row = blockIdx.x;
    const int q = row & (Ss - 1);
    float* p = attn + (size_t)row * Ss;
    __shared__ float buf[Ss];
    __shared__ float red[256];
    const int tid = threadIdx.x;
    const int n = q + 1;

    float mx = -INFINITY;
    for (int i = tid; i < n; i += 256) {
        float v = p[i];
        buf[i] = v;
        mx = fmaxf(mx, v);
    }
    red[tid] = mx;
    __syncthreads();
#pragma unroll
    for (int s = 128; s > 0; s >>= 1) {
        if (tid < s) red[tid] = fmaxf(red[tid], red[tid + s]);
        __syncthreads();
    }
    mx = red[0];
    __syncthreads();

    float sum = 0.f;
    for (int i = tid; i < n; i += 256) {
        float e = __expf(buf[i] - mx);
        buf[i] = e;
        sum += e;
    }
    red[tid] = sum;
    __syncthreads();
#pragma unroll
    for (int s = 128; s > 0; s >>= 1) {
        if (tid < s) red[tid] += red[tid + s];
        __syncthreads();
    }
    float inv = 1.0f / red[0];

    for (int i = tid; i < n; i += 256) p[i] = buf[i] * inv;
}

// ==================== ctx ====================
__global__ void __launch_bounds__(256) ctx_kernel(
    const float* __restrict__ attn, const float* __restrict__ V, float* __restrict__ ctx)
{
    const int bh = blockIdx.z;
    const int qm = blockIdx.y * 64;
    const int tid = threadIdx.x;
    const float* A = attn + (size_t)bh * Ss * Ss;
    const float* Bm = V + (size_t)bh * Ss * HD;

    __shared__ float As[16][68];
    __shared__ float Bs[16][68];
    const int tx = tid & 15;
    const int ty = tid >> 4;
    const int lr = tid >> 2;
    const int lk = (tid & 3) << 2;
    const int br = tid >> 4;
    const int bc = (tid & 15) << 2;

    float acc[4][4];
#pragma unroll
    for (int i = 0; i < 4; i++)
#pragma unroll
        for (int j = 0; j < 4; j++) acc[i][j] = 0.f;

    const int kmax = qm + 64;
    for (int k0 = 0; k0 < kmax; k0 += 16) {
        float4 a = *reinterpret_cast<const float4*>(A + (size_t)(qm + lr) * Ss + k0 + lk);
        As[lk + 0][lr] = a.x; As[lk + 1][lr] = a.y; As[lk + 2][lr] = a.z; As[lk + 3][lr] = a.w;
        float4 b = *reinterpret_cast<const float4*>(Bm + (size_t)(k0 + br) * HD + bc);
        *reinterpret_cast<float4*>(&Bs[br][bc]) = b;
        __syncthreads();
#pragma unroll
        for (int kk = 0; kk < 16; kk++) {
            float4 av = *reinterpret_cast<const float4*>(&As[kk][ty << 2]);
            float4 bv = *reinterpret_cast<const float4*>(&Bs[kk][tx << 2]);
            float am[4] = {av.x, av.y, av.z, av.w};
            float bm_[4] = {bv.x, bv.y, bv.z, bv.w};
#pragma unroll
            for (int i = 0; i < 4; i++)
#pragma unroll
                for (int j = 0; j < 4; j++)
                    acc[i][j] = fmaf(am[i], bm_[j], acc[i][j]);
        }
        __syncthreads();
    }

    const int b = bh >> 4;
    const int h = bh & 15;
#pragma unroll
    for (int i = 0; i < 4; i++) {
        int s = qm + (ty << 2) + i;
#pragma unroll
        for (int j = 0; j < 4; j++) {
            int d = (tx << 2) + j;
            ctx[((size_t)(b * Ss + s)) * Ee + h * HD + d] = acc[i][j];
        }
    }
}

// ==================== host ====================
extern "C" void kernel_launch(void* const* d_in, const int* in_sizes, int n_in,
                              void* d_out, int out_size)
{
    const float* query = (const float*)d_in[0];
    const float* key_t = (const float*)d_in[1];
    const float* value = (const float*)d_in[2];
    const float* Wq = (const float*)d_in[4];
    const float* bq = (const float*)d_in[5];
    const float* Wk = (const float*)d_in[6];
    const float* bk = (const float*)d_in[7];
    const float* Wv = (const float*)d_in[8];
    const float* bv = (const float*)d_in[9];
    const float* Wo = (const float*)d_in[10];
    const float* bo = (const float*)d_in[11];
    float* out = (float*)d_out;

    float *qp, *kp, *vp, *ctxp, *attn_fb;
    __nv_bfloat16 *ahi, *alo, *whi, *wlo;
    cudaGetSymbolAddress((void**)&qp, g_q);
    cudaGetSymbolAddress((void**)&kp, g_k);
    cudaGetSymbolAddress((void**)&vp, g_v);
    cudaGetSymbolAddress((void**)&ctxp, g_ctx);
    cudaGetSymbolAddress((void**)&attn_fb, g_attn);
    cudaGetSymbolAddress((void**)&ahi, g_ahi);
    cudaGetSymbolAddress((void**)&alo, g_alo);
    cudaGetSymbolAddress((void**)&whi, g_whi);
    cudaGetSymbolAddress((void**)&wlo, g_wlo);

    cudaFuncSetAttribute(gemm_mma, cudaFuncAttributeMaxDynamicSharedMemorySize, GEMM_SMEM);

    const long long needed = (long long)Bb * Ss * Ee + (long long)BH * Ss * Ss;
    float* attnp = ((long long)out_size >= needed) ? (out + (size_t)Bb * Ss * Ee) : attn_fb;

    const int nA4 = Bb * Ss * Ee / 4;
    const int nW4 = Ee * Ee / 4;
    dim3 gg(Ee / 128, (Bb * Ss) / 128);     // 8 x 32

    // Q projection
    split_bf16<<<nA4 / 256, 256>>>((const float4*)query, ahi, alo, nA4);
    split_bf16<<<nW4 / 256, 256>>>((const float4*)Wq, whi, wlo, nW4);
    gemm_mma<<<gg, 256, GEMM_SMEM>>>(ahi, alo, whi, wlo, bq, qp, 1);

    // K projection
    split_bf16<<<nA4 / 256, 256>>>((const float4*)key_t, ahi, alo, nA4);
    split_bf16<<<nW4 / 256, 256>>>((const float4*)Wk, whi, wlo, nW4);
    gemm_mma<<<gg, 256, GEMM_SMEM>>>(ahi, alo, whi, wlo, bk, kp, 1);

    // V projection
    split_bf16<<<nA4 / 256, 256>>>((const float4*)value, ahi, alo, nA4);
    split_bf16<<<nW4 / 256, 256>>>((const float4*)Wv, whi, wlo, nW4);
    gemm_mma<<<gg, 256, GEMM_SMEM>>>(ahi, alo, whi, wlo, bv, vp, 1);

    // attention (SIMT)
    dim3 blk(256);
    dim3 gs(Ss / 64, Ss / 64, BH);
    scores_kernel<<<gs, blk>>>(qp, kp, attnp);
    softmax_kernel<<<BH * Ss, blk>>>(attnp);
    dim3 gc(1, Ss / 64, BH);
    ctx_kernel<<<gc, blk>>>(attnp, vp, ctxp);

    // output projection
    split_bf16<<<nA4 / 256, 256>>>((const float4*)ctxp, ahi, alo, nA4);
    split_bf16<<<nW4 / 256, 256>>>((const float4*)Wo, whi, wlo, nW4);
    gemm_mma<<<gg, 256, GEMM_SMEM>>>(ahi, alo, whi, wlo, bo, out, 0);
}

// round 4
// speedup vs baseline: 1.9248x; 1.2201x over previous
#include <cuda_runtime.h>
#include <cuda_bf16.h>
#include <math.h>
#include <stdint.h>

#define Bb 4
#define Ss 1024
#define Ee 1024
#define Hh 16
#define HD 64
#define BH (Bb*Hh)

// ---------------- scratch (no allocs allowed) ----------------
__device__ float g_attn[67108864];               // fallback if attn not in d_out
__device__ __nv_bfloat16 g_ahi[Bb * Ss * Ee];
__device__ __nv_bfloat16 g_alo[Bb * Ss * Ee];
__device__ __nv_bfloat16 g_whi[Ee * Ee];
__device__ __nv_bfloat16 g_wlo[Ee * Ee];
__device__ __nv_bfloat16 g_qhi[BH * Ss * HD];
__device__ __nv_bfloat16 g_qlo[BH * Ss * HD];
__device__ __nv_bfloat16 g_khi[BH * Ss * HD];
__device__ __nv_bfloat16 g_klo[BH * Ss * HD];
__device__ __nv_bfloat16 g_vhi[BH * Ss * HD];
__device__ __nv_bfloat16 g_vlo[BH * Ss * HD];
__device__ __nv_bfloat16 g_chi[Bb * Ss * Ee];
__device__ __nv_bfloat16 g_clo[Bb * Ss * Ee];

// ==================== helpers ====================
static __device__ __forceinline__ uint32_t s2u(const void* p) {
    uint32_t a;
    asm("{ .reg .u64 t; cvta.to.shared.u64 t, %1; cvt.u32.u64 %0, t; }" : "=r"(a) : "l"(p));
    return a;
}

static __device__ __forceinline__ void cp16(uint32_t saddr, const void* g) {
    asm volatile("cp.async.cg.shared.global [%0], [%1], 16;" :: "r"(saddr), "l"(g) : "memory");
}

static __device__ __forceinline__ void mma_bf16(float c[4], const uint32_t a[4], const uint32_t b[2]) {
    asm volatile(
        "mma.sync.aligned.m16n8k16.row.col.f32.bf16.bf16.f32 "
        "{%0,%1,%2,%3}, {%4,%5,%6,%7}, {%8,%9}, {%0,%1,%2,%3};"
        : "+f"(c[0]), "+f"(c[1]), "+f"(c[2]), "+f"(c[3])
        : "r"(a[0]), "r"(a[1]), "r"(a[2]), "r"(a[3]), "r"(b[0]), "r"(b[1]));
}

static __device__ __forceinline__ void ldmx2t(uint32_t& r0, uint32_t& r1, uint32_t addr) {
    asm volatile("ldmatrix.sync.aligned.m8n8.x2.trans.shared.b16 {%0,%1}, [%2];"
                 : "=r"(r0), "=r"(r1) : "r"(addr));
}

static __device__ __forceinline__ uint32_t pack_hi(float x, float y) {
    __nv_bfloat16 hx = __float2bfloat16(x), hy = __float2bfloat16(y);
    return (uint32_t)__bfloat16_as_ushort(hx) | ((uint32_t)__bfloat16_as_ushort(hy) << 16);
}
static __device__ __forceinline__ uint32_t pack_lo(float x, float y) {
    __nv_bfloat16 hx = __float2bfloat16(x), hy = __float2bfloat16(y);
    float lx = x - __bfloat162float(hx), ly = y - __bfloat162float(hy);
    return (uint32_t)__bfloat16_as_ushort(__float2bfloat16(lx))
         | ((uint32_t)__bfloat16_as_ushort(__float2bfloat16(ly)) << 16);
}

// ==================== split: x -> (hi, lo) bf16 ====================
__global__ void __launch_bounds__(256) split_bf16(
    const float4* __restrict__ x, __nv_bfloat16* __restrict__ hi,
    __nv_bfloat16* __restrict__ lo, int n4)
{
    int i = blockIdx.x * 256 + threadIdx.x;
    if (i >= n4) return;
    float4 v = x[i];
    uint32_t h0 = pack_hi(v.x, v.y), h1 = pack_hi(v.z, v.w);
    uint32_t l0 = pack_lo(v.x, v.y), l1 = pack_lo(v.z, v.w);
    uint2 hs = make_uint2(h0, h1), ls = make_uint2(l0, l1);
    *reinterpret_cast<uint2*>(hi + 4 * (size_t)i) = hs;
    *reinterpret_cast<uint2*>(lo + 4 * (size_t)i) = ls;
}

// ==================== bf16x3 mma GEMM ====================
// Tile 128x128, BK=32, 8 warps (4m x 2n), cp.async double-buffered.
// mode 0: fp32 C [4096][1024].  mode 1: bf16 hi/lo, head-split [BH][S][64].
#define ARR_B   10240
#define STAGE_B 40960
#define GEMM_SMEM (2 * STAGE_B)

__global__ void __launch_bounds__(256, 1) gemm_mma(
    const __nv_bfloat16* __restrict__ Ahi, const __nv_bfloat16* __restrict__ Alo,
    const __nv_bfloat16* __restrict__ Whi, const __nv_bfloat16* __restrict__ Wlo,
    const float* __restrict__ bias, float* __restrict__ C,
    __nv_bfloat16* __restrict__ Chi, __nv_bfloat16* __restrict__ Clo, int mode)
{
    extern __shared__ __align__(128) char smem[];
    const uint32_t sb = s2u(smem);
    const int tid = threadIdx.x;
    const int lane = tid & 31, wid = tid >> 5;
    const int wm = wid & 3, wn = wid >> 2;
    const int bm = blockIdx.y << 7, bn = blockIdx.x << 7;
    const int K = 1024;

    const int c0 = tid << 1;
    const int lrow = c0 >> 2, lcc = c0 & 3;
    const __nv_bfloat16* pAh = Ahi + (size_t)(bm + lrow) * K + lcc * 8;
    const __nv_bfloat16* pAl = Alo + (size_t)(bm + lrow) * K + lcc * 8;
    const __nv_bfloat16* pWh = Whi + (size_t)(bn + lrow) * K + lcc * 8;
    const __nv_bfloat16* pWl = Wlo + (size_t)(bn + lrow) * K + lcc * 8;
    const uint32_t so = (uint32_t)(lrow * 80 + lcc * 16);

#define LOAD_STAGE(s, kt) do {                                          \
        uint32_t b_ = sb + (uint32_t)(s) * STAGE_B + so;                \
        const int ko_ = (kt) * 32;                                      \
        cp16(b_ + 0 * ARR_B,      pAh + ko_);                           \
        cp16(b_ + 0 * ARR_B + 16, pAh + ko_ + 8);                       \
        cp16(b_ + 1 * ARR_B,      pAl + ko_);                           \
        cp16(b_ + 1 * ARR_B + 16, pAl + ko_ + 8);                       \
        cp16(b_ + 2 * ARR_B,      pWh + ko_);                           \
        cp16(b_ + 2 * ARR_B + 16, pWh + ko_ + 8);                       \
        cp16(b_ + 3 * ARR_B,      pWl + ko_);                           \
        cp16(b_ + 3 * ARR_B + 16, pWl + ko_ + 8);                       \
        asm volatile("cp.async.commit_group;" ::: "memory");            \
    } while (0)

    float acc[2][8][4];
#pragma unroll
    for (int a = 0; a < 2; a++)
#pragma unroll
        for (int b = 0; b < 8; b++)
#pragma unroll
            for (int c = 0; c < 4; c++) acc[a][b][c] = 0.f;

    LOAD_STAGE(0, 0);

    const int fr = lane >> 2, fq = lane & 3;

    for (int kt = 0; kt < 32; kt++) {
        const int s = kt & 1;
        if (kt < 31) {
            LOAD_STAGE(s ^ 1, kt + 1);
            asm volatile("cp.async.wait_group 1;" ::: "memory");
        } else {
            asm volatile("cp.async.wait_group 0;" ::: "memory");
        }
        __syncthreads();

        const uint32_t* SAh = (const uint32_t*)(smem + (size_t)s * STAGE_B);
        const uint32_t* SAl = SAh + ARR_B / 4;
        const uint32_t* SWh = SAh + 2 * ARR_B / 4;
        const uint32_t* SWl = SAh + 3 * ARR_B / 4;

#pragma unroll
        for (int ks = 0; ks < 2; ks++) {
            const int w0 = ks * 8 + fq;
            uint32_t ah[2][4], al[2][4];
#pragma unroll
            for (int mt = 0; mt < 2; mt++) {
                int ra = wm * 32 + mt * 16 + fr;
                ah[mt][0] = SAh[ra * 20 + w0];
                ah[mt][1] = SAh[(ra + 8) * 20 + w0];
                ah[mt][2] = SAh[ra * 20 + w0 + 4];
                ah[mt][3] = SAh[(ra + 8) * 20 + w0 + 4];
                al[mt][0] = SAl[ra * 20 + w0];
                al[mt][1] = SAl[(ra + 8) * 20 + w0];
                al[mt][2] = SAl[ra * 20 + w0 + 4];
                al[mt][3] = SAl[(ra + 8) * 20 + w0 + 4];
            }
            uint32_t bhf[8][2], blf[8][2];
#pragma unroll
            for (int nt = 0; nt < 8; nt++) {
                int rb = wn * 64 + nt * 8 + fr;
                bhf[nt][0] = SWh[rb * 20 + w0];
                bhf[nt][1] = SWh[rb * 20 + w0 + 4];
                blf[nt][0] = SWl[rb * 20 + w0];
                blf[nt][1] = SWl[rb * 20 + w0 + 4];
            }
#pragma unroll
            for (int mt = 0; mt < 2; mt++)
#pragma unroll
                for (int nt = 0; nt < 8; nt++) {
                    mma_bf16(acc[mt][nt], ah[mt], bhf[nt]);
                    mma_bf16(acc[mt][nt], ah[mt], blf[nt]);
                    mma_bf16(acc[mt][nt], al[mt], bhf[nt]);
                }
        }
        __syncthreads();
    }

    // epilogue
    const int q2 = (lane & 3) * 2;
#pragma unroll
    for (int mt = 0; mt < 2; mt++) {
#pragma unroll
        for (int i = 0; i < 2; i++) {
            int m = bm + wm * 32 + mt * 16 + fr + i * 8;
#pragma unroll
            for (int nt = 0; nt < 8; nt++) {
                int n = bn + wn * 64 + nt * 8 + q2;
                float vx = acc[mt][nt][i * 2 + 0] + bias[n];
                float vy = acc[mt][nt][i * 2 + 1] + bias[n + 1];
                if (mode) {
                    size_t idx = ((((size_t)(m >> 10) * Hh + (n >> 6)) * Ss
                                   + (size_t)(m & 1023)) << 6) + (n & 63);
                    *reinterpret_cast<uint32_t*>(Chi + idx) = pack_hi(vx, vy);
                    *reinterpret_cast<uint32_t*>(Clo + idx) = pack_lo(vx, vy);
                } else {
                    float2 v = make_float2(vx, vy);
                    *reinterpret_cast<float2*>(C + (size_t)m * Ee + n) = v;
                }
            }
        }
    }
#undef LOAD_STAGE
}

// ==================== fused attention ====================
// Block = (bh, 32 q rows). Phase1: S = Q K^T (bf16x3 mma) -> smem fp32, causal+scale.
// Phase2: softmax in smem, write attn (single pass). Phase3: ctx = P V (bf16x3 mma,
// P converted from smem, V via ldmatrix.trans), write ctx as bf16 hi/lo merged-head.
#define S_STRIDE 1036
#define SM_Q_OFF 132608
#define SM_K_OFF 141824
#define FUSED_SMEM 178688

__global__ void __launch_bounds__(256, 1) fused_attn(
    const __nv_bfloat16* __restrict__ qhi, const __nv_bfloat16* __restrict__ qlo,
    const __nv_bfloat16* __restrict__ khi, const __nv_bfloat16* __restrict__ klo,
    const __nv_bfloat16* __restrict__ vhi, const __nv_bfloat16* __restrict__ vlo,
    float* __restrict__ attn, __nv_bfloat16* __restrict__ chi, __nv_bfloat16* __restrict__ clo)
{
    extern __shared__ __align__(16) char sm[];
    float* S = (float*)sm;
    const uint32_t* Qh = (const uint32_t*)(sm + SM_Q_OFF);
    const uint32_t* Ql = Qh + 32 * 36;
    const uint32_t* Kh = (const uint32_t*)(sm + SM_K_OFF);
    const uint32_t* Kl = Kh + 128 * 36;
    const uint32_t sQu = s2u(sm + SM_Q_OFF);
    const uint32_t sKu = s2u(sm + SM_K_OFF);

    const int tid = threadIdx.x, lane = tid & 31, wid = tid >> 5;
    const int fr = lane >> 2, fq = lane & 3;
    const int bh = blockIdx.y, qt = blockIdx.x;
    const int q0 = qt << 5;
    const int nchunk = (q0 + 159) >> 7;          // k-chunks of 128 needed (causal)
    const size_t kvbase = (size_t)bh * Ss * HD;

    // ---- stage Q (32x64 hi/lo) + K chunk 0 ----
    {
        int row = tid >> 3, seg = tid & 7;
        const __nv_bfloat16* qh_g = qhi + kvbase + (size_t)q0 * 64;
        const __nv_bfloat16* ql_g = qlo + kvbase + (size_t)q0 * 64;
        cp16(sQu + row * 144 + seg * 16, qh_g + row * 64 + seg * 8);
        cp16(sQu + 4608 + row * 144 + seg * 16, ql_g + row * 64 + seg * 8);
#pragma unroll
        for (int p = 0; p < 4; p++) {
            int r2 = (tid >> 3) + p * 32;
            cp16(sKu + r2 * 144 + seg * 16, khi + kvbase + (size_t)r2 * 64 + seg * 8);
            cp16(sKu + 18432 + r2 * 144 + seg * 16, klo + kvbase + (size_t)r2 * 64 + seg * 8);
        }
        asm volatile("cp.async.commit_group;" ::: "memory");
    }

    // ---- phase 1: scores ----
    const int wm = wid & 1, wnq = wid >> 1;      // 2m x 4n(32)
    for (int c = 0; c < nchunk; c++) {
        if (c > 0) {
            int seg = tid & 7;
#pragma unroll
            for (int p = 0; p < 4; p++) {
                int r2 = (tid >> 3) + p * 32;
                size_t gr = kvbase + ((size_t)c * 128 + r2) * 64 + seg * 8;
                cp16(sKu + r2 * 144 + seg * 16, khi + gr);
                cp16(sKu + 18432 + r2 * 144 + seg * 16, klo + gr);
            }
            asm volatile("cp.async.commit_group;" ::: "memory");
        }
        asm volatile("cp.async.wait_group 0;" ::: "memory");
        __syncthreads();

        float acc[4][4];
#pragma unroll
        for (int u = 0; u < 4; u++)
#pragma unroll
            for (int j = 0; j < 4; j++) acc[u][j] = 0.f;

#pragma unroll
        for (int kst = 0; kst < 4; kst++) {
            const int w0 = kst * 8 + fq;
            int ra = wm * 16 + fr;
            uint32_t ah[4], al[4];
            ah[0] = Qh[ra * 36 + w0];        ah[1] = Qh[(ra + 8) * 36 + w0];
            ah[2] = Qh[ra * 36 + w0 + 4];    ah[3] = Qh[(ra + 8) * 36 + w0 + 4];
            al[0] = Ql[ra * 36 + w0];        al[1] = Ql[(ra + 8) * 36 + w0];
            al[2] = Ql[ra * 36 + w0 + 4];    al[3] = Ql[(ra + 8) * 36 + w0 + 4];
#pragma unroll
            for (int u = 0; u < 4; u++) {
                int rb = wnq * 32 + u * 8 + fr;
                uint32_t bhf[2] = {Kh[rb * 36 + w0], Kh[rb * 36 + w0 + 4]};
                uint32_t blf[2] = {Kl[rb * 36 + w0], Kl[rb * 36 + w0 + 4]};
                mma_bf16(acc[u], ah, bhf);
                mma_bf16(acc[u], ah, blf);
                mma_bf16(acc[u], al, bhf);
            }
        }

        // store to S with causal mask + scale
        const int lr0 = wm * 16 + fr;
        const int gr0 = q0 + lr0, gr1 = gr0 + 8;
#pragma unroll
        for (int u = 0; u < 4; u++) {
            int col = c * 128 + wnq * 32 + u * 8 + fq * 2;
            float2 v0, v1;
            v0.x = (col     <= gr0) ? acc[u][0] * 0.125f : -INFINITY;
            v0.y = (col + 1 <= gr0) ? acc[u][1] * 0.125f : -INFINITY;
            v1.x = (col     <= gr1) ? acc[u][2] * 0.125f : -INFINITY;
            v1.y = (col + 1 <= gr1) ? acc[u][3] * 0.125f : -INFINITY;
            *reinterpret_cast<float2*>(&S[lr0 * S_STRIDE + col]) = v0;
            *reinterpret_cast<float2*>(&S[(lr0 + 8) * S_STRIDE + col]) = v1;
        }
        __syncthreads();
    }

    // ---- phase 2: softmax + attn write ----
    const int climit = nchunk * 128;
#pragma unroll 1
    for (int i = 0; i < 4; i++) {
        int r = wid * 4 + i;
        int gq = q0 + r;
        float* Sr = S + r * S_STRIDE;
        float mx = -INFINITY;
        for (int c = lane * 4; c < climit; c += 128) {
            float4 v = *reinterpret_cast<float4*>(&Sr[c]);
            mx = fmaxf(mx, fmaxf(fmaxf(v.x, v.y), fmaxf(v.z, v.w)));
        }
#pragma unroll
        for (int o = 16; o > 0; o >>= 1) mx = fmaxf(mx, __shfl_xor_sync(~0u, mx, o));
        float sum = 0.f;
        for (int c = lane * 4; c < climit; c += 128) {
            float4 v = *reinterpret_cast<float4*>(&Sr[c]);
            v.x = __expf(v.x - mx); v.y = __expf(v.y - mx);
            v.z = __expf(v.z - mx); v.w = __expf(v.w - mx);
            sum += v.x + v.y + v.z + v.w;
            *reinterpret_cast<float4*>(&Sr[c]) = v;
        }
#pragma unroll
        for (int o = 16; o > 0; o >>= 1) sum += __shfl_xor_sync(~0u, sum, o);
        float inv = 1.0f / sum;
        float* arow = attn + ((size_t)bh * Ss + gq) * Ss;
        for (int c = lane * 4; c < climit; c += 128) {
            float4 v = *reinterpret_cast<float4*>(&Sr[c]);
            v.x *= inv; v.y *= inv; v.z *= inv; v.w *= inv;
            *reinterpret_cast<float4*>(&Sr[c]) = v;
            *reinterpret_cast<float4*>(&arow[c]) = v;
        }
        float4 z = make_float4(0.f, 0.f, 0.f, 0.f);
        for (int c = climit + lane * 4; c < Ss; c += 128)
            *reinterpret_cast<float4*>(&arow[c]) = z;
    }
    __syncthreads();

    // ---- phase 3: ctx = P @ V ----
    const int wm3 = wid & 1, wn3 = wid >> 1;     // 2m x 4n(16)
    float cacc[2][4];
#pragma unroll
    for (int u = 0; u < 2; u++)
#pragma unroll
        for (int j = 0; j < 4; j++) cacc[u][j] = 0.f;

    const int l16 = lane & 15;
    for (int c = 0; c < nchunk; c++) {
        {
            int seg = tid & 7;
#pragma unroll
            for (int p = 0; p < 4; p++) {
                int r2 = (tid >> 3) + p * 32;
                size_t gr = kvbase + ((size_t)c * 128 + r2) * 64 + seg * 8;
                cp16(sKu + r2 * 144 + seg * 16, vhi + gr);
                cp16(sKu + 18432 + r2 * 144 + seg * 16, vlo + gr);
            }
            asm volatile("cp.async.commit_group;" ::: "memory");
            asm volatile("cp.async.wait_group 0;" ::: "memory");
        }
        __syncthreads();

#pragma unroll 1
        for (int kk = 0; kk < 8; kk++) {
            const int kt0 = kk * 16;
            const int scol = c * 128 + kt0 + 2 * fq;
            const int r0 = wm3 * 16 + fr;
            float2 p00 = *reinterpret_cast<float2*>(&S[r0 * S_STRIDE + scol]);
            float2 p10 = *reinterpret_cast<float2*>(&S[(r0 + 8) * S_STRIDE + scol]);
            float2 p01 = *reinterpret_cast<float2*>(&S[r0 * S_STRIDE + scol + 8]);
            float2 p11 = *reinterpret_cast<float2*>(&S[(r0 + 8) * S_STRIDE + scol + 8]);
            uint32_t ah[4], al[4];
            ah[0] = pack_hi(p00.x, p00.y); al[0] = pack_lo(p00.x, p00.y);
            ah[1] = pack_hi(p10.x, p10.y); al[1] = pack_lo(p10.x, p10.y);
            ah[2] = pack_hi(p01.x, p01.y); al[2] = pack_lo(p01.x, p01.y);
            ah[3] = pack_hi(p11.x, p11.y); al[3] = pack_lo(p11.x, p11.y);
#pragma unroll
            for (int u = 0; u < 2; u++) {
                int seg = wn3 * 2 + u;
                uint32_t addr = sKu + (uint32_t)(kt0 + l16) * 144 + seg * 16;
                uint32_t bhf[2], blf[2];
                ldmx2t(bhf[0], bhf[1], addr);
                ldmx2t(blf[0], blf[1], addr + 18432);
                mma_bf16(cacc[u], ah, bhf);
                mma_bf16(cacc[u], ah, blf);
                mma_bf16(cacc[u], al, bhf);
            }
        }
        __syncthreads();
    }

    // ---- epilogue: ctx -> bf16 hi/lo, merged-head [B][S][E] ----
    {
        const int b = bh >> 4, h = bh & 15;
        const int t0 = q0 + wm3 * 16 + fr;
#pragma unroll
        for (int u = 0; u < 2; u++) {
            int d = wn3 * 16 + u * 8 + fq * 2;
            size_t i0 = ((size_t)(b * Ss + t0) * Ee) + h * 64 + d;
            size_t i1 = ((size_t)(b * Ss + t0 + 8) * Ee) + h * 64 + d;
            *reinterpret_cast<uint32_t*>(chi + i0) = pack_hi(cacc[u][0], cacc[u][1]);
            *reinterpret_cast<uint32_t*>(clo + i0) = pack_lo(cacc[u][0], cacc[u][1]);
            *reinterpret_cast<uint32_t*>(chi + i1) = pack_hi(cacc[u][2], cacc[u][3]);
            *reinterpret_cast<uint32_t*>(clo + i1) = pack_lo(cacc[u][2], cacc[u][3]);
        }
    }
}

// ==================== host ====================
extern "C" void kernel_launch(void* const* d_in, const int* in_sizes, int n_in,
                              void* d_out, int out_size)
{
    const float* query = (const float*)d_in[0];
    const float* key_t = (const float*)d_in[1];
    const float* value = (const float*)d_in[2];
    const float* Wq = (const float*)d_in[4];
    const float* bq = (const float*)d_in[5];
    const float* Wk = (const float*)d_in[6];
    const float* bk = (const float*)d_in[7];
    const float* Wv = (const float*)d_in[8];
    const float* bv = (const float*)d_in[9];
    const float* Wo = (const float*)d_in[10];
    const float* bo = (const float*)d_in[11];
    float* out = (float*)d_out;

    float* attn_fb;
    __nv_bfloat16 *ahi, *alo, *whi, *wlo, *qhi, *qlo, *khi, *klo, *vhi, *vlo, *chi, *clo;
    cudaGetSymbolAddress((void**)&attn_fb, g_attn);
    cudaGetSymbolAddress((void**)&ahi, g_ahi);
    cudaGetSymbolAddress((void**)&alo, g_alo);
    cudaGetSymbolAddress((void**)&whi, g_whi);
    cudaGetSymbolAddress((void**)&wlo, g_wlo);
    cudaGetSymbolAddress((void**)&qhi, g_qhi);
    cudaGetSymbolAddress((void**)&qlo, g_qlo);
    cudaGetSymbolAddress((void**)&khi, g_khi);
    cudaGetSymbolAddress((void**)&klo, g_klo);
    cudaGetSymbolAddress((void**)&vhi, g_vhi);
    cudaGetSymbolAddress((void**)&vlo, g_vlo);
    cudaGetSymbolAddress((void**)&chi, g_chi);
    cudaGetSymbolAddress((void**)&clo, g_clo);

    cudaFuncSetAttribute(gemm_mma, cudaFuncAttributeMaxDynamicSharedMemorySize, GEMM_SMEM);
    cudaFuncSetAttribute(fused_attn, cudaFuncAttributeMaxDynamicSharedMemorySize, FUSED_SMEM);

    const long long needed = (long long)Bb * Ss * Ee + (long long)BH * Ss * Ss;
    float* attnp = ((long long)out_size >= needed) ? (out + (size_t)Bb * Ss * Ee) : attn_fb;

    const int nA4 = Bb * Ss * Ee / 4;
    const int nW4 = Ee * Ee / 4;
    dim3 gg(Ee / 128, (Bb * Ss) / 128);

    // Q projection -> qhi/qlo
    split_bf16<<<nA4 / 256, 256>>>((const float4*)query, ahi, alo, nA4);
    split_bf16<<<nW4 / 256, 256>>>((const float4*)Wq, whi, wlo, nW4);
    gemm_mma<<<gg, 256, GEMM_SMEM>>>(ahi, alo, whi, wlo, bq, nullptr, qhi, qlo, 1);

    // K projection -> khi/klo
    split_bf16<<<nA4 / 256, 256>>>((const float4*)key_t, ahi, alo, nA4);
    split_bf16<<<nW4 / 256, 256>>>((const float4*)Wk, whi, wlo, nW4);
    gemm_mma<<<gg, 256, GEMM_SMEM>>>(ahi, alo, whi, wlo, bk, nullptr, khi, klo, 1);

    // V projection -> vhi/vlo
    split_bf16<<<nA4 / 256, 256>>>((const float4*)value, ahi, alo, nA4);
    split_bf16<<<nW4 / 256, 256>>>((const float4*)Wv, whi, wlo, nW4);
    gemm_mma<<<gg, 256, GEMM_SMEM>>>(ahi, alo, whi, wlo, bv, nullptr, vhi, vlo, 1);

    // fused attention -> attn + ctx(hi/lo)
    dim3 gf(Ss / 32, BH);
    fused_attn<<<gf, 256, FUSED_SMEM>>>(qhi, qlo, khi, klo, vhi, vlo, attnp, chi, clo);

    // output projection (A = ctx hi/lo directly)
    split_bf16<<<nW4 / 256, 256>>>((const float4*)Wo, whi, wlo, nW4);
    gemm_mma<<<gg, 256, GEMM_SMEM>>>(chi, clo, whi, wlo, bo, out, nullptr, nullptr, 0);
}

// round 5
// speedup vs baseline: 3.3367x; 1.7335x over previous
#include <cuda_runtime.h>
#include <cuda_fp16.h>
#include <math.h>
#include <stdint.h>

#define Bb 4
#define Ss 1024
#define Ee 1024
#define Hh 16
#define HD 64
#define BH (Bb*Hh)

// ---------------- scratch (no allocs allowed) ----------------
__device__ float g_attn[67108864];               // fallback if attn not in d_out
__device__ __half g_a16[Bb * Ss * Ee];
__device__ __half g_w16[Ee * Ee];
__device__ __half g_q16[BH * Ss * HD];
__device__ __half g_k16[BH * Ss * HD];
__device__ __half g_v16[BH * Ss * HD];
__device__ __half g_c16[Bb * Ss * Ee];

// ==================== helpers ====================
static __device__ __forceinline__ uint32_t s2u(const void* p) {
    uint32_t a;
    asm("{ .reg .u64 t; cvta.to.shared.u64 t, %1; cvt.u32.u64 %0, t; }" : "=r"(a) : "l"(p));
    return a;
}

static __device__ __forceinline__ void cp16(uint32_t saddr, const void* g) {
    asm volatile("cp.async.cg.shared.global [%0], [%1], 16;" :: "r"(saddr), "l"(g) : "memory");
}

static __device__ __forceinline__ void mma_f16(float c[4], const uint32_t a[4], const uint32_t b[2]) {
    asm volatile(
        "mma.sync.aligned.m16n8k16.row.col.f32.f16.f16.f32 "
        "{%0,%1,%2,%3}, {%4,%5,%6,%7}, {%8,%9}, {%0,%1,%2,%3};"
        : "+f"(c[0]), "+f"(c[1]), "+f"(c[2]), "+f"(c[3])
        : "r"(a[0]), "r"(a[1]), "r"(a[2]), "r"(a[3]), "r"(b[0]), "r"(b[1]));
}

static __device__ __forceinline__ void ldmx2t(uint32_t& r0, uint32_t& r1, uint32_t addr) {
    asm volatile("ldmatrix.sync.aligned.m8n8.x2.trans.shared.b16 {%0,%1}, [%2];"
                 : "=r"(r0), "=r"(r1) : "r"(addr));
}

static __device__ __forceinline__ uint32_t packh(float x, float y) {
    __half2 h = __floats2half2_rn(x, y);
    return *reinterpret_cast<uint32_t*>(&h);
}

// ==================== convert: fp32 -> fp16 ====================
__global__ void __launch_bounds__(256) tohalf(
    const float4* __restrict__ x, __half* __restrict__ o, int n4)
{
    int i = blockIdx.x * 256 + threadIdx.x;
    if (i >= n4) return;
    float4 v = x[i];
    uint2 r = make_uint2(packh(v.x, v.y), packh(v.z, v.w));
    *reinterpret_cast<uint2*>(o + 4 * (size_t)i) = r;
}

// ==================== fp16 mma GEMM ====================
// C[4096,1024] = A[4096,1024] @ W[1024,1024]^T + bias.
// Tile 128x128, BK=32, 8 warps (4m x 2n), cp.async double-buffered.
// mode 0: fp32 C.  mode 1: fp16 C16, head-split [BH][S][64].
#define ARR_B   10240
#define STAGE_B 20480
#define GEMM_SMEM (2 * STAGE_B)

__global__ void __launch_bounds__(256, 1) gemm_mma(
    const __half* __restrict__ A, const __half* __restrict__ W,
    const float* __restrict__ bias, float* __restrict__ C,
    __half* __restrict__ C16, int mode)
{
    extern __shared__ __align__(128) char smem[];
    const uint32_t sb = s2u(smem);
    const int tid = threadIdx.x;
    const int lane = tid & 31, wid = tid >> 5;
    const int wm = wid & 3, wn = wid >> 2;
    const int bm = blockIdx.y << 7, bn = blockIdx.x << 7;
    const int K = 1024;

    const int c0 = tid << 1;
    const int lrow = c0 >> 2, lcc = c0 & 3;
    const __half* pA = A + (size_t)(bm + lrow) * K + lcc * 8;
    const __half* pW = W + (size_t)(bn + lrow) * K + lcc * 8;
    const uint32_t so = (uint32_t)(lrow * 80 + lcc * 16);

#define LOAD_STAGE(s, kt) do {                                          \
        uint32_t b_ = sb + (uint32_t)(s) * STAGE_B + so;                \
        const int ko_ = (kt) * 32;                                      \
        cp16(b_,              pA + ko_);                                \
        cp16(b_ + 16,         pA + ko_ + 8);                            \
        cp16(b_ + ARR_B,      pW + ko_);                                \
        cp16(b_ + ARR_B + 16, pW + ko_ + 8);                            \
        asm volatile("cp.async.commit_group;" ::: "memory");            \
    } while (0)

    float acc[2][8][4];
#pragma unroll
    for (int a = 0; a < 2; a++)
#pragma unroll
        for (int b = 0; b < 8; b++)
#pragma unroll
            for (int c = 0; c < 4; c++) acc[a][b][c] = 0.f;

    LOAD_STAGE(0, 0);

    const int fr = lane >> 2, fq = lane & 3;

    for (int kt = 0; kt < 32; kt++) {
        const int s = kt & 1;
        if (kt < 31) {
            LOAD_STAGE(s ^ 1, kt + 1);
            asm volatile("cp.async.wait_group 1;" ::: "memory");
        } else {
            asm volatile("cp.async.wait_group 0;" ::: "memory");
        }
        __syncthreads();

        const uint32_t* SA = (const uint32_t*)(smem + (size_t)s * STAGE_B);
        const uint32_t* SW = SA + ARR_B / 4;

#pragma unroll
        for (int ks = 0; ks < 2; ks++) {
            const int w0 = ks * 8 + fq;
            uint32_t ah[2][4];
#pragma unroll
            for (int mt = 0; mt < 2; mt++) {
                int ra = wm * 32 + mt * 16 + fr;
                ah[mt][0] = SA[ra * 20 + w0];
                ah[mt][1] = SA[(ra + 8) * 20 + w0];
                ah[mt][2] = SA[ra * 20 + w0 + 4];
                ah[mt][3] = SA[(ra + 8) * 20 + w0 + 4];
            }
            uint32_t bf[8][2];
#pragma unroll
            for (int nt = 0; nt < 8; nt++) {
                int rb = wn * 64 + nt * 8 + fr;
                bf[nt][0] = SW[rb * 20 + w0];
                bf[nt][1] = SW[rb * 20 + w0 + 4];
            }
#pragma unroll
            for (int mt = 0; mt < 2; mt++)
#pragma unroll
                for (int nt = 0; nt < 8; nt++)
                    mma_f16(acc[mt][nt], ah[mt], bf[nt]);
        }
        __syncthreads();
    }

    // epilogue
    const int q2 = (lane & 3) * 2;
#pragma unroll
    for (int mt = 0; mt < 2; mt++) {
#pragma unroll
        for (int i = 0; i < 2; i++) {
            int m = bm + wm * 32 + mt * 16 + fr + i * 8;
#pragma unroll
            for (int nt = 0; nt < 8; nt++) {
                int n = bn + wn * 64 + nt * 8 + q2;
                float vx = acc[mt][nt][i * 2 + 0] + bias[n];
                float vy = acc[mt][nt][i * 2 + 1] + bias[n + 1];
                if (mode) {
                    size_t idx = ((((size_t)(m >> 10) * Hh + (n >> 6)) * Ss
                                   + (size_t)(m & 1023)) << 6) + (n & 63);
                    *reinterpret_cast<uint32_t*>(C16 + idx) = packh(vx, vy);
                } else {
                    float2 v = make_float2(vx, vy);
                    *reinterpret_cast<float2*>(C + (size_t)m * Ee + n) = v;
                }
            }
        }
    }
#undef LOAD_STAGE
}

// ==================== fused attention (fp16 mma) ====================
#define S_STRIDE 1036
#define SM_Q_OFF 132608
#define SM_K_OFF 137216
#define FUSED_SMEM 155648

__global__ void __launch_bounds__(256, 1) fused_attn(
    const __half* __restrict__ q16, const __half* __restrict__ k16,
    const __half* __restrict__ v16,
    float* __restrict__ attn, __half* __restrict__ c16)
{
    extern __shared__ __align__(16) char sm[];
    float* S = (float*)sm;
    const uint32_t* Qh = (const uint32_t*)(sm + SM_Q_OFF);
    const uint32_t* Kh = (const uint32_t*)(sm + SM_K_OFF);
    const uint32_t sQu = s2u(sm + SM_Q_OFF);
    const uint32_t sKu = s2u(sm + SM_K_OFF);

    const int tid = threadIdx.x, lane = tid & 31, wid = tid >> 5;
    const int fr = lane >> 2, fq = lane & 3;
    const int bh = blockIdx.y, qt = blockIdx.x;
    const int q0 = qt << 5;
    const int nchunk = (q0 + 159) >> 7;
    const size_t kvbase = (size_t)bh * Ss * HD;

    // ---- stage Q (32x64) + K chunk 0 ----
    {
        int row = tid >> 3, seg = tid & 7;
        cp16(sQu + row * 144 + seg * 16, q16 + kvbase + (size_t)(q0 + row) * 64 + seg * 8);
#pragma unroll
        for (int p = 0; p < 4; p++) {
            int r2 = (tid >> 3) + p * 32;
            cp16(sKu + r2 * 144 + seg * 16, k16 + kvbase + (size_t)r2 * 64 + seg * 8);
        }
        asm volatile("cp.async.commit_group;" ::: "memory");
    }

    // ---- phase 1: scores ----
    const int wm = wid & 1, wnq = wid >> 1;      // 2m x 4n(32)
    for (int c = 0; c < nchunk; c++) {
        if (c > 0) {
            int seg = tid & 7;
#pragma unroll
            for (int p = 0; p < 4; p++) {
                int r2 = (tid >> 3) + p * 32;
                cp16(sKu + r2 * 144 + seg * 16,
                     k16 + kvbase + ((size_t)c * 128 + r2) * 64 + seg * 8);
            }
            asm volatile("cp.async.commit_group;" ::: "memory");
        }
        asm volatile("cp.async.wait_group 0;" ::: "memory");
        __syncthreads();

        float acc[4][4];
#pragma unroll
        for (int u = 0; u < 4; u++)
#pragma unroll
            for (int j = 0; j < 4; j++) acc[u][j] = 0.f;

#pragma unroll
        for (int kst = 0; kst < 4; kst++) {
            const int w0 = kst * 8 + fq;
            int ra = wm * 16 + fr;
            uint32_t ah[4];
            ah[0] = Qh[ra * 36 + w0];        ah[1] = Qh[(ra + 8) * 36 + w0];
            ah[2] = Qh[ra * 36 + w0 + 4];    ah[3] = Qh[(ra + 8) * 36 + w0 + 4];
#pragma unroll
            for (int u = 0; u < 4; u++) {
                int rb = wnq * 32 + u * 8 + fr;
                uint32_t bf[2] = {Kh[rb * 36 + w0], Kh[rb * 36 + w0 + 4]};
                mma_f16(acc[u], ah, bf);
            }
        }

        const int lr0 = wm * 16 + fr;
        const int gr0 = q0 + lr0, gr1 = gr0 + 8;
#pragma unroll
        for (int u = 0; u < 4; u++) {
            int col = c * 128 + wnq * 32 + u * 8 + fq * 2;
            float2 v0, v1;
            v0.x = (col     <= gr0) ? acc[u][0] * 0.125f : -INFINITY;
            v0.y = (col + 1 <= gr0) ? acc[u][1] * 0.125f : -INFINITY;
            v1.x = (col     <= gr1) ? acc[u][2] * 0.125f : -INFINITY;
            v1.y = (col + 1 <= gr1) ? acc[u][3] * 0.125f : -INFINITY;
            *reinterpret_cast<float2*>(&S[lr0 * S_STRIDE + col]) = v0;
            *reinterpret_cast<float2*>(&S[(lr0 + 8) * S_STRIDE + col]) = v1;
        }
        __syncthreads();
    }

    // ---- phase 2: softmax + attn write ----
    const int climit = nchunk * 128;
#pragma unroll 1
    for (int i = 0; i < 4; i++) {
        int r = wid * 4 + i;
        int gq = q0 + r;
        float* Sr = S + r * S_STRIDE;
        float mx = -INFINITY;
        for (int c = lane * 4; c < climit; c += 128) {
            float4 v = *reinterpret_cast<float4*>(&Sr[c]);
            mx = fmaxf(mx, fmaxf(fmaxf(v.x, v.y), fmaxf(v.z, v.w)));
        }
#pragma unroll
        for (int o = 16; o > 0; o >>= 1) mx = fmaxf(mx, __shfl_xor_sync(~0u, mx, o));
        float sum = 0.f;
        for (int c = lane * 4; c < climit; c += 128) {
            float4 v = *reinterpret_cast<float4*>(&Sr[c]);
            v.x = __expf(v.x - mx); v.y = __expf(v.y - mx);
            v.z = __expf(v.z - mx); v.w = __expf(v.w - mx);
            sum += v.x + v.y + v.z + v.w;
            *reinterpret_cast<float4*>(&Sr[c]) = v;
        }
#pragma unroll
        for (int o = 16; o > 0; o >>= 1) sum += __shfl_xor_sync(~0u, sum, o);
        float inv = 1.0f / sum;
        float* arow = attn + ((size_t)bh * Ss + gq) * Ss;
        for (int c = lane * 4; c < climit; c += 128) {
            float4 v = *reinterpret_cast<float4*>(&Sr[c]);
            v.x *= inv; v.y *= inv; v.z *= inv; v.w *= inv;
            *reinterpret_cast<float4*>(&Sr[c]) = v;
            *reinterpret_cast<float4*>(&arow[c]) = v;
        }
        float4 z = make_float4(0.f, 0.f, 0.f, 0.f);
        for (int c = climit + lane * 4; c < Ss; c += 128)
            *reinterpret_cast<float4*>(&arow[c]) = z;
    }
    __syncthreads();

    // ---- phase 3: ctx = P @ V ----
    const int wm3 = wid & 1, wn3 = wid >> 1;     // 2m x 4n(16)
    float cacc[2][4];
#pragma unroll
    for (int u = 0; u < 2; u++)
#pragma unroll
        for (int j = 0; j < 4; j++) cacc[u][j] = 0.f;

    const int l16 = lane & 15;
    for (int c = 0; c < nchunk; c++) {
        {
            int seg = tid & 7;
#pragma unroll
            for (int p = 0; p < 4; p++) {
                int r2 = (tid >> 3) + p * 32;
                cp16(sKu + r2 * 144 + seg * 16,
                     v16 + kvbase + ((size_t)c * 128 + r2) * 64 + seg * 8);
            }
            asm volatile("cp.async.commit_group;" ::: "memory");
            asm volatile("cp.async.wait_group 0;" ::: "memory");
        }
        __syncthreads();

#pragma unroll 1
        for (int kk = 0; kk < 8; kk++) {
            const int kt0 = kk * 16;
            const int scol = c * 128 + kt0 + 2 * fq;
            const int r0 = wm3 * 16 + fr;
            float2 p00 = *reinterpret_cast<float2*>(&S[r0 * S_STRIDE + scol]);
            float2 p10 = *reinterpret_cast<float2*>(&S[(r0 + 8) * S_STRIDE + scol]);
            float2 p01 = *reinterpret_cast<float2*>(&S[r0 * S_STRIDE + scol + 8]);
            float2 p11 = *reinterpret_cast<float2*>(&S[(r0 + 8) * S_STRIDE + scol + 8]);
            uint32_t ah[4];
            ah[0] = packh(p00.x, p00.y);
            ah[1] = packh(p10.x, p10.y);
            ah[2] = packh(p01.x, p01.y);
            ah[3] = packh(p11.x, p11.y);
#pragma unroll
            for (int u = 0; u < 2; u++) {
                int seg = wn3 * 2 + u;
                uint32_t addr = sKu + (uint32_t)(kt0 + l16) * 144 + seg * 16;
                uint32_t bf[2];
                ldmx2t(bf[0], bf[1], addr);
                mma_f16(cacc[u], ah, bf);
            }
        }
        __syncthreads();
    }

    // ---- epilogue: ctx -> fp16, merged-head [B][S][E] ----
    {
        const int b = bh >> 4, h = bh & 15;
        const int t0 = q0 + wm3 * 16 + fr;
#pragma unroll
        for (int u = 0; u < 2; u++) {
            int d = wn3 * 16 + u * 8 + fq * 2;
            size_t i0 = ((size_t)(b * Ss + t0) * Ee) + h * 64 + d;
            size_t i1 = ((size_t)(b * Ss + t0 + 8) * Ee) + h * 64 + d;
            *reinterpret_cast<uint32_t*>(c16 + i0) = packh(cacc[u][0], cacc[u][1]);
            *reinterpret_cast<uint32_t*>(c16 + i1) = packh(cacc[u][2], cacc[u][3]);
        }
    }
}

// ==================== host ====================
extern "C" void kernel_launch(void* const* d_in, const int* in_sizes, int n_in,
                              void* d_out, int out_size)
{
    const float* query = (const float*)d_in[0];
    const float* key_t = (const float*)d_in[1];
    const float* value = (const float*)d_in[2];
    const float* Wq = (const float*)d_in[4];
    const float* bq = (const float*)d_in[5];
    const float* Wk = (const float*)d_in[6];
    const float* bk = (const float*)d_in[7];
    const float* Wv = (const float*)d_in[8];
    const float* bv = (const float*)d_in[9];
    const float* Wo = (const float*)d_in[10];
    const float* bo = (const float*)d_in[11];
    float* out = (float*)d_out;

    float* attn_fb;
    __half *a16, *w16, *q16, *k16, *v16, *c16;
    cudaGetSymbolAddress((void**)&attn_fb, g_attn);
    cudaGetSymbolAddress((void**)&a16, g_a16);
    cudaGetSymbolAddress((void**)&w16, g_w16);
    cudaGetSymbolAddress((void**)&q16, g_q16);
    cudaGetSymbolAddress((void**)&k16, g_k16);
    cudaGetSymbolAddress((void**)&v16, g_v16);
    cudaGetSymbolAddress((void**)&c16, g_c16);

    cudaFuncSetAttribute(gemm_mma, cudaFuncAttributeMaxDynamicSharedMemorySize, GEMM_SMEM);
    cudaFuncSetAttribute(fused_attn, cudaFuncAttributeMaxDynamicSharedMemorySize, FUSED_SMEM);

    const long long needed = (long long)Bb * Ss * Ee + (long long)BH * Ss * Ss;
    float* attnp = ((long long)out_size >= needed) ? (out + (size_t)Bb * Ss * Ee) : attn_fb;

    const int nA4 = Bb * Ss * Ee / 4;
    const int nW4 = Ee * Ee / 4;
    dim3 gg(Ee / 128, (Bb * Ss) / 128);

    // Q projection
    tohalf<<<nA4 / 256, 256>>>((const float4*)query, a16, nA4);
    tohalf<<<nW4 / 256, 256>>>((const float4*)Wq, w16, nW4);
    gemm_mma<<<gg, 256, GEMM_SMEM>>>(a16, w16, bq, nullptr, q16, 1);

    // K projection
    tohalf<<<nA4 / 256, 256>>>((const float4*)key_t, a16, nA4);
    tohalf<<<nW4 / 256, 256>>>((const float4*)Wk, w16, nW4);
    gemm_mma<<<gg, 256, GEMM_SMEM>>>(a16, w16, bk, nullptr, k16, 1);

    // V projection
    tohalf<<<nA4 / 256, 256>>>((const float4*)value, a16, nA4);
    tohalf<<<nW4 / 256, 256>>>((const float4*)Wv, w16, nW4);
    gemm_mma<<<gg, 256, GEMM_SMEM>>>(a16, w16, bv, nullptr, v16, 1);

    // fused attention -> attn + ctx(fp16)
    dim3 gf(Ss / 32, BH);
    fused_attn<<<gf, 256, FUSED_SMEM>>>(q16, k16, v16, attnp, c16);

    // output projection
    tohalf<<<nW4 / 256, 256>>>((const float4*)Wo, w16, nW4);
    gemm_mma<<<gg, 256, GEMM_SMEM>>>(c16, w16, bo, out, nullptr, 0);
}

// round 6
// speedup vs baseline: 4.1896x; 1.2556x over previous
#include <cuda_runtime.h>
#include <cuda_fp16.h>
#include <math.h>
#include <stdint.h>

#define Bb 4
#define Ss 1024
#define Ee 1024
#define Hh 16
#define HD 64
#define BH (Bb*Hh)

// ---------------- scratch (no allocs allowed) ----------------
__device__ float g_attn[67108864];               // fallback if attn not in d_out
__device__ __half g_aq[Bb * Ss * Ee];
__device__ __half g_ak[Bb * Ss * Ee];
__device__ __half g_av[Bb * Ss * Ee];
__device__ __half g_wq[Ee * Ee];
__device__ __half g_wk[Ee * Ee];
__device__ __half g_wv[Ee * Ee];
__device__ __half g_wo[Ee * Ee];
__device__ __half g_q16[BH * Ss * HD];
__device__ __half g_k16[BH * Ss * HD];
__device__ __half g_v16[BH * Ss * HD];
__device__ __half g_c16[Bb * Ss * Ee];

// ==================== helpers ====================
static __device__ __forceinline__ uint32_t s2u(const void* p) {
    uint32_t a;
    asm("{ .reg .u64 t; cvta.to.shared.u64 t, %1; cvt.u32.u64 %0, t; }" : "=r"(a) : "l"(p));
    return a;
}

static __device__ __forceinline__ void cp16(uint32_t saddr, const void* g) {
    asm volatile("cp.async.cg.shared.global [%0], [%1], 16;" :: "r"(saddr), "l"(g) : "memory");
}

static __device__ __forceinline__ void mma_f16(float c[4], const uint32_t a[4], const uint32_t b[2]) {
    asm volatile(
        "mma.sync.aligned.m16n8k16.row.col.f32.f16.f16.f32 "
        "{%0,%1,%2,%3}, {%4,%5,%6,%7}, {%8,%9}, {%0,%1,%2,%3};"
        : "+f"(c[0]), "+f"(c[1]), "+f"(c[2]), "+f"(c[3])
        : "r"(a[0]), "r"(a[1]), "r"(a[2]), "r"(a[3]), "r"(b[0]), "r"(b[1]));
}

static __device__ __forceinline__ void ldmx2t(uint32_t& r0, uint32_t& r1, uint32_t addr) {
    asm volatile("ldmatrix.sync.aligned.m8n8.x2.trans.shared.b16 {%0,%1}, [%2];"
                 : "=r"(r0), "=r"(r1) : "r"(addr));
}

static __device__ __forceinline__ uint32_t packh(float x, float y) {
    __half2 h = __floats2half2_rn(x, y);
    return *reinterpret_cast<uint32_t*>(&h);
}

// ==================== batched convert: fp32 -> fp16 ====================
struct ConvArgs {
    const float4 *s0, *s1, *s2, *s3;
    __half *d0, *d1, *d2, *d3;
};

__global__ void __launch_bounds__(256) conv_batch(ConvArgs a, int n4)
{
    const float4* src; __half* dst;
    switch (blockIdx.y) {
        case 0:  src = a.s0; dst = a.d0; break;
        case 1:  src = a.s1; dst = a.d1; break;
        case 2:  src = a.s2; dst = a.d2; break;
        default: src = a.s3; dst = a.d3; break;
    }
    int i = blockIdx.x * 256 + threadIdx.x;
    if (i >= n4) return;
    float4 v = src[i];
    uint2 r = make_uint2(packh(v.x, v.y), packh(v.z, v.w));
    *reinterpret_cast<uint2*>(dst + 4 * (size_t)i) = r;
}

// ==================== fp16 mma GEMM body ====================
// C[4096,1024] = A @ W^T + bias. Tile 128x128, BK=32, 8 warps (4m x 2n).
// 4-stage cp.async pipeline, prefetch distance 2, one barrier per k-iter.
// MODE 0: fp32 C.  MODE 1: fp16 C16, head-split [BH][S][64].
#define ARR_B   10240
#define STAGE_B 20480
#define GEMM_SMEM (4 * STAGE_B)

template<int MODE>
static __device__ __forceinline__ void gemm_body(
    const __half* __restrict__ A, const __half* __restrict__ W,
    const float* __restrict__ bias, float* __restrict__ C, __half* __restrict__ C16)
{
    extern __shared__ __align__(128) char smem[];
    const uint32_t sb = s2u(smem);
    const int tid = threadIdx.x;
    const int lane = tid & 31, wid = tid >> 5;
    const int wm = wid & 3, wn = wid >> 2;
    const int bm = blockIdx.y << 7, bn = blockIdx.x << 7;
    const int K = 1024;

    const int c0 = tid << 1;
    const int lrow = c0 >> 2, lcc = c0 & 3;
    const __half* pA = A + (size_t)(bm + lrow) * K + lcc * 8;
    const __half* pW = W + (size_t)(bn + lrow) * K + lcc * 8;
    const uint32_t so = (uint32_t)(lrow * 80 + lcc * 16);

#define LOAD_STAGE(s, kt) do {                                          \
        uint32_t b_ = sb + (uint32_t)(s) * STAGE_B + so;                \
        const int ko_ = (kt) * 32;                                      \
        cp16(b_,              pA + ko_);                                \
        cp16(b_ + 16,         pA + ko_ + 8);                            \
        cp16(b_ + ARR_B,      pW + ko_);                                \
        cp16(b_ + ARR_B + 16, pW + ko_ + 8);                            \
        asm volatile("cp.async.commit_group;" ::: "memory");            \
    } while (0)

    float acc[2][8][4];
#pragma unroll
    for (int a = 0; a < 2; a++)
#pragma unroll
        for (int b = 0; b < 8; b++)
#pragma unroll
            for (int c = 0; c < 4; c++) acc[a][b][c] = 0.f;

    LOAD_STAGE(0, 0);
    LOAD_STAGE(1, 1);

    const int fr = lane >> 2, fq = lane & 3;

    for (int kt = 0; kt < 32; kt++) {
        const int s = kt & 3;
        if (kt <= 29) LOAD_STAGE((kt + 2) & 3, kt + 2);
        if (kt < 30)       asm volatile("cp.async.wait_group 2;" ::: "memory");
        else if (kt == 30) asm volatile("cp.async.wait_group 1;" ::: "memory");
        else               asm volatile("cp.async.wait_group 0;" ::: "memory");
        __syncthreads();

        const uint32_t* SA = (const uint32_t*)(smem + (size_t)s * STAGE_B);
        const uint32_t* SW = SA + ARR_B / 4;

#pragma unroll
        for (int ks = 0; ks < 2; ks++) {
            const int w0 = ks * 8 + fq;
            uint32_t ah[2][4];
#pragma unroll
            for (int mt = 0; mt < 2; mt++) {
                int ra = wm * 32 + mt * 16 + fr;
                ah[mt][0] = SA[ra * 20 + w0];
                ah[mt][1] = SA[(ra + 8) * 20 + w0];
                ah[mt][2] = SA[ra * 20 + w0 + 4];
                ah[mt][3] = SA[(ra + 8) * 20 + w0 + 4];
            }
            uint32_t bf[8][2];
#pragma unroll
            for (int nt = 0; nt < 8; nt++) {
                int rb = wn * 64 + nt * 8 + fr;
                bf[nt][0] = SW[rb * 20 + w0];
                bf[nt][1] = SW[rb * 20 + w0 + 4];
            }
#pragma unroll
            for (int mt = 0; mt < 2; mt++)
#pragma unroll
                for (int nt = 0; nt < 8; nt++)
                    mma_f16(acc[mt][nt], ah[mt], bf[nt]);
        }
    }

    // epilogue
    const int q2 = (lane & 3) * 2;
#pragma unroll
    for (int mt = 0; mt < 2; mt++) {
#pragma unroll
        for (int i = 0; i < 2; i++) {
            int m = bm + wm * 32 + mt * 16 + fr + i * 8;
#pragma unroll
            for (int nt = 0; nt < 8; nt++) {
                int n = bn + wn * 64 + nt * 8 + q2;
                float vx = acc[mt][nt][i * 2 + 0] + bias[n];
                float vy = acc[mt][nt][i * 2 + 1] + bias[n + 1];
                if (MODE) {
                    size_t idx = ((((size_t)(m >> 10) * Hh + (n >> 6)) * Ss
                                   + (size_t)(m & 1023)) << 6) + (n & 63);
                    *reinterpret_cast<uint32_t*>(C16 + idx) = packh(vx, vy);
                } else {
                    float2 v = make_float2(vx, vy);
                    *reinterpret_cast<float2*>(C + (size_t)m * Ee + n) = v;
                }
            }
        }
    }
#undef LOAD_STAGE
}

struct QKVArgs {
    const __half *A0, *A1, *A2;
    const __half *W0, *W1, *W2;
    const float  *b0, *b1, *b2;
    __half *O0, *O1, *O2;
};

__global__ void __launch_bounds__(256) gemm_qkv(QKVArgs a)
{
    const __half *A, *W; const float* b; __half* O;
    switch (blockIdx.z) {
        case 0:  A = a.A0; W = a.W0; b = a.b0; O = a.O0; break;
        case 1:  A = a.A1; W = a.W1; b = a.b1; O = a.O1; break;
        default: A = a.A2; W = a.W2; b = a.b2; O = a.O2; break;
    }
    gemm_body<1>(A, W, b, nullptr, O);
}

__global__ void __launch_bounds__(256) gemm_o(
    const __half* __restrict__ A, const __half* __restrict__ W,
    const float* __restrict__ bias, float* __restrict__ C)
{
    gemm_body<0>(A, W, bias, C, nullptr);
}

// ==================== fused attention (fp16 mma, double-buffered K/V) ====================
#define S_STRIDE 1036
#define SM_Q_OFF 132608
#define SM_K_OFF 137216
#define KV_BUF   18432
#define FUSED_SMEM (SM_K_OFF + 2 * KV_BUF)

__global__ void __launch_bounds__(256, 1) fused_attn(
    const __half* __restrict__ q16, const __half* __restrict__ k16,
    const __half* __restrict__ v16,
    float* __restrict__ attn, __half* __restrict__ c16)
{
    extern __shared__ __align__(16) char sm[];
    float* S = (float*)sm;
    const uint32_t* Qh = (const uint32_t*)(sm + SM_Q_OFF);
    const uint32_t sQu = s2u(sm + SM_Q_OFF);
    const uint32_t sKu = s2u(sm + SM_K_OFF);

    const int tid = threadIdx.x, lane = tid & 31, wid = tid >> 5;
    const int fr = lane >> 2, fq = lane & 3;
    const int bh = blockIdx.y, qt = blockIdx.x;
    const int q0 = qt << 5;
    const int nchunk = (q0 + 159) >> 7;
    const size_t kvbase = (size_t)bh * Ss * HD;
    const int lseg = tid & 7, lr8 = tid >> 3;

    // ---- stage Q (32x64) + K chunk 0 into buf0 ----
    {
        cp16(sQu + lr8 * 144 + lseg * 16, q16 + kvbase + (size_t)(q0 + lr8) * 64 + lseg * 8);
#pragma unroll
        for (int p = 0; p < 4; p++) {
            int r2 = lr8 + p * 32;
            cp16(sKu + r2 * 144 + lseg * 16, k16 + kvbase + (size_t)r2 * 64 + lseg * 8);
        }
        asm volatile("cp.async.commit_group;" ::: "memory");
    }

    // ---- phase 1: scores (K double-buffered) ----
    const int wm = wid & 1, wnq = wid >> 1;      // 2m x 4n(32)
    for (int c = 0; c < nchunk; c++) {
        if (c + 1 < nchunk) {
            uint32_t dst = sKu + ((c + 1) & 1) * KV_BUF;
#pragma unroll
            for (int p = 0; p < 4; p++) {
                int r2 = lr8 + p * 32;
                cp16(dst + r2 * 144 + lseg * 16,
                     k16 + kvbase + ((size_t)(c + 1) * 128 + r2) * 64 + lseg * 8);
            }
            asm volatile("cp.async.commit_group;" ::: "memory");
            asm volatile("cp.async.wait_group 1;" ::: "memory");
        } else {
            asm volatile("cp.async.wait_group 0;" ::: "memory");
        }
        __syncthreads();

        const uint32_t* Kb = (const uint32_t*)(sm + SM_K_OFF + (size_t)(c & 1) * KV_BUF);

        float acc[4][4];
#pragma unroll
        for (int u = 0; u < 4; u++)
#pragma unroll
            for (int j = 0; j < 4; j++) acc[u][j] = 0.f;

#pragma unroll
        for (int kst = 0; kst < 4; kst++) {
            const int w0 = kst * 8 + fq;
            int ra = wm * 16 + fr;
            uint32_t ah[4];
            ah[0] = Qh[ra * 36 + w0];        ah[1] = Qh[(ra + 8) * 36 + w0];
            ah[2] = Qh[ra * 36 + w0 + 4];    ah[3] = Qh[(ra + 8) * 36 + w0 + 4];
#pragma unroll
            for (int u = 0; u < 4; u++) {
                int rb = wnq * 32 + u * 8 + fr;
                uint32_t bf[2] = {Kb[rb * 36 + w0], Kb[rb * 36 + w0 + 4]};
                mma_f16(acc[u], ah, bf);
            }
        }

        const int lr0 = wm * 16 + fr;
        const int gr0 = q0 + lr0, gr1 = gr0 + 8;
#pragma unroll
        for (int u = 0; u < 4; u++) {
            int col = c * 128 + wnq * 32 + u * 8 + fq * 2;
            float2 v0, v1;
            v0.x = (col     <= gr0) ? acc[u][0] * 0.125f : -INFINITY;
            v0.y = (col + 1 <= gr0) ? acc[u][1] * 0.125f : -INFINITY;
            v1.x = (col     <= gr1) ? acc[u][2] * 0.125f : -INFINITY;
            v1.y = (col + 1 <= gr1) ? acc[u][3] * 0.125f : -INFINITY;
            *reinterpret_cast<float2*>(&S[lr0 * S_STRIDE + col]) = v0;
            *reinterpret_cast<float2*>(&S[(lr0 + 8) * S_STRIDE + col]) = v1;
        }
        __syncthreads();
    }

    // ---- prefetch V chunk 0 (overlaps with softmax) ----
    {
#pragma unroll
        for (int p = 0; p < 4; p++) {
            int r2 = lr8 + p * 32;
            cp16(sKu + r2 * 144 + lseg * 16, v16 + kvbase + (size_t)r2 * 64 + lseg * 8);
        }
        asm volatile("cp.async.commit_group;" ::: "memory");
    }

    // ---- phase 2: softmax + attn write ----
    const int climit = nchunk * 128;
#pragma unroll 1
    for (int i = 0; i < 4; i++) {
        int r = wid * 4 + i;
        int gq = q0 + r;
        float* Sr = S + r * S_STRIDE;
        float mx = -INFINITY;
        for (int c = lane * 4; c < climit; c += 128) {
            float4 v = *reinterpret_cast<float4*>(&Sr[c]);
            mx = fmaxf(mx, fmaxf(fmaxf(v.x, v.y), fmaxf(v.z, v.w)));
        }
#pragma unroll
        for (int o = 16; o > 0; o >>= 1) mx = fmaxf(mx, __shfl_xor_sync(~0u, mx, o));
        float sum = 0.f;
        for (int c = lane * 4; c < climit; c += 128) {
            float4 v = *reinterpret_cast<float4*>(&Sr[c]);
            v.x = __expf(v.x - mx); v.y = __expf(v.y - mx);
            v.z = __expf(v.z - mx); v.w = __expf(v.w - mx);
            sum += v.x + v.y + v.z + v.w;
            *reinterpret_cast<float4*>(&Sr[c]) = v;
        }
#pragma unroll
        for (int o = 16; o > 0; o >>= 1) sum += __shfl_xor_sync(~0u, sum, o);
        float inv = 1.0f / sum;
        float* arow = attn + ((size_t)bh * Ss + gq) * Ss;
        for (int c = lane * 4; c < climit; c += 128) {
            float4 v = *reinterpret_cast<float4*>(&Sr[c]);
            v.x *= inv; v.y *= inv; v.z *= inv; v.w *= inv;
            *reinterpret_cast<float4*>(&Sr[c]) = v;
            *reinterpret_cast<float4*>(&arow[c]) = v;
        }
        float4 z = make_float4(0.f, 0.f, 0.f, 0.f);
        for (int c = climit + lane * 4; c < Ss; c += 128)
            *reinterpret_cast<float4*>(&arow[c]) = z;
    }
    __syncthreads();

    // ---- phase 3: ctx = P @ V (V double-buffered) ----
    const int wm3 = wid & 1, wn3 = wid >> 1;     // 2m x 4n(16)
    float cacc[2][4];
#pragma unroll
    for (int u = 0; u < 2; u++)
#pragma unroll
        for (int j = 0; j < 4; j++) cacc[u][j] = 0.f;

    const int l16 = lane & 15;
    for (int c = 0; c < nchunk; c++) {
        if (c + 1 < nchunk) {
            uint32_t dst = sKu + ((c + 1) & 1) * KV_BUF;
#pragma unroll
            for (int p = 0; p < 4; p++) {
                int r2 = lr8 + p * 32;
                cp16(dst + r2 * 144 + lseg * 16,
                     v16 + kvbase + ((size_t)(c + 1) * 128 + r2) * 64 + lseg * 8);
            }
            asm volatile("cp.async.commit_group;" ::: "memory");
            asm volatile("cp.async.wait_group 1;" ::: "memory");
        } else {
            asm volatile("cp.async.wait_group 0;" ::: "memory");
        }
        __syncthreads();

        const uint32_t vbase = sKu + (uint32_t)(c & 1) * KV_BUF;

#pragma unroll 1
        for (int kk = 0; kk < 8; kk++) {
            const int kt0 = kk * 16;
            const int scol = c * 128 + kt0 + 2 * fq;
            const int r0 = wm3 * 16 + fr;
            float2 p00 = *reinterpret_cast<float2*>(&S[r0 * S_STRIDE + scol]);
            float2 p10 = *reinterpret_cast<float2*>(&S[(r0 + 8) * S_STRIDE + scol]);
            float2 p01 = *reinterpret_cast<float2*>(&S[r0 * S_STRIDE + scol + 8]);
            float2 p11 = *reinterpret_cast<float2*>(&S[(r0 + 8) * S_STRIDE + scol + 8]);
            uint32_t ah[4];
            ah[0] = packh(p00.x, p00.y);
            ah[1] = packh(p10.x, p10.y);
            ah[2] = packh(p01.x, p01.y);
            ah[3] = packh(p11.x, p11.y);
#pragma unroll
            for (int u = 0; u < 2; u++) {
                int seg = wn3 * 2 + u;
                uint32_t addr = vbase + (uint32_t)(kt0 + l16) * 144 + seg * 16;
                uint32_t bf[2];
                ldmx2t(bf[0], bf[1], addr);
                mma_f16(cacc[u], ah, bf);
            }
        }
        __syncthreads();
    }

    // ---- epilogue: ctx -> fp16, merged-head [B][S][E] ----
    {
        const int b = bh >> 4, h = bh & 15;
        const int t0 = q0 + wm3 * 16 + fr;
#pragma unroll
        for (int u = 0; u < 2; u++) {
            int d = wn3 * 16 + u * 8 + fq * 2;
            size_t i0 = ((size_t)(b * Ss + t0) * Ee) + h * 64 + d;
            size_t i1 = ((size_t)(b * Ss + t0 + 8) * Ee) + h * 64 + d;
            *reinterpret_cast<uint32_t*>(c16 + i0) = packh(cacc[u][0], cacc[u][1]);
            *reinterpret_cast<uint32_t*>(c16 + i1) = packh(cacc[u][2], cacc[u][3]);
        }
    }
}

// ==================== host ====================
extern "C" void kernel_launch(void* const* d_in, const int* in_sizes, int n_in,
                              void* d_out, int out_size)
{
    const float* query = (const float*)d_in[0];
    const float* key_t = (const float*)d_in[1];
    const float* value = (const float*)d_in[2];
    const float* Wq = (const float*)d_in[4];
    const float* bq = (const float*)d_in[5];
    const float* Wk = (const float*)d_in[6];
    const float* bk = (const float*)d_in[7];
    const float* Wv = (const float*)d_in[8];
    const float* bv = (const float*)d_in[9];
    const float* Wo = (const float*)d_in[10];
    const float* bo = (const float*)d_in[11];
    float* out = (float*)d_out;

    float* attn_fb;
    __half *aq, *ak, *av, *wq, *wk, *wv, *wo, *q16, *k16, *v16, *c16;
    cudaGetSymbolAddress((void**)&attn_fb, g_attn);
    cudaGetSymbolAddress((void**)&aq, g_aq);
    cudaGetSymbolAddress((void**)&ak, g_ak);
    cudaGetSymbolAddress((void**)&av, g_av);
    cudaGetSymbolAddress((void**)&wq, g_wq);
    cudaGetSymbolAddress((void**)&wk, g_wk);
    cudaGetSymbolAddress((void**)&wv, g_wv);
    cudaGetSymbolAddress((void**)&wo, g_wo);
    cudaGetSymbolAddress((void**)&q16, g_q16);
    cudaGetSymbolAddress((void**)&k16, g_k16);
    cudaGetSymbolAddress((void**)&v16, g_v16);
    cudaGetSymbolAddress((void**)&c16, g_c16);

    cudaFuncSetAttribute(gemm_qkv, cudaFuncAttributeMaxDynamicSharedMemorySize, GEMM_SMEM);
    cudaFuncSetAttribute(gemm_o, cudaFuncAttributeMaxDynamicSharedMemorySize, GEMM_SMEM);
    cudaFuncSetAttribute(fused_attn, cudaFuncAttributeMaxDynamicSharedMemorySize, FUSED_SMEM);

    const long long needed = (long long)Bb * Ss * Ee + (long long)BH * Ss * Ss;
    float* attnp = ((long long)out_size >= needed) ? (out + (size_t)Bb * Ss * Ee) : attn_fb;

    // batched conversions: 3 inputs (4M floats each), 4 weights (1M floats each)
    ConvArgs cin = { (const float4*)query, (const float4*)key_t, (const float4*)value,
                     (const float4*)query, aq, ak, av, aq };
    conv_batch<<<dim3(4096, 3), 256>>>(cin, 1048576);
    ConvArgs cw = { (const float4*)Wq, (const float4*)Wk, (const float4*)Wv,
                    (const float4*)Wo, wq, wk, wv, wo };
    conv_batch<<<dim3(1024, 4), 256>>>(cw, 262144);

    // batched QKV projections
    QKVArgs qa = { aq, ak, av, wq, wk, wv, bq, bk, bv, q16, k16, v16 };
    gemm_qkv<<<dim3(8, 32, 3), 256, GEMM_SMEM>>>(qa);

    // fused attention -> attn + ctx(fp16)
    fused_attn<<<dim3(Ss / 32, BH), 256, FUSED_SMEM>>>(q16, k16, v16, attnp, c16);

    // output projection
    gemm_o<<<dim3(8, 32), 256, GEMM_SMEM>>>(c16, wo, bo, out);
}